// round 7
// baseline (speedup 1.0000x reference)
#include <cuda_runtime.h>
#include <math.h>
#include <stdint.h>

// Problem constants (fixed shapes)
#define NB   4
#define LQL  2048
#define DM   1024
#define HH   16
#define PP   64
#define MROWS (NB*LQL)        // 8192
#define EPSBN 1e-5f

// ---------------- scratch (device globals: allocation-free) ----------------
__device__ float gQ  [MROWS * DM];   // tf32-rounded Q projection
__device__ float gK  [MROWS * DM];   // tf32-rounded K projection
__device__ float gV  [MROWS * DM];   // tf32-rounded V projection
__device__ float gRes[MROWS * DM];
__device__ float gAQ [MROWS * DM];   // tf32-rounded query (GEMM A input)
__device__ float gAK [MROWS * DM];   // tf32-rounded key   (GEMM A input)
__device__ float gWR [3 * DM * DM];  // tf32-rounded Wq,Wk,Wv (GEMM B input)
__device__ float gPartS[64 * DM];
__device__ float gPartQ[64 * DM];
__device__ float gColA[DM];
__device__ float gColB[DM];

// ---------------- shared helpers ----------------
static __device__ __forceinline__ uint32_t smem_u32(const void* p) {
    uint32_t r;
    asm("{ .reg .u64 t; cvta.to.shared.u64 t, %1; cvt.u32.u64 %0, t; }"
        : "=r"(r) : "l"(p));
    return r;
}
static __device__ __forceinline__ uint32_t f2tf(float x) {
    uint32_t r;
    asm("cvt.rna.tf32.f32 %0, %1;" : "=r"(r) : "f"(x));
    return r;
}
static __device__ __forceinline__ void mma_tf32(float* d, const uint32_t* a,
                                                const uint32_t* b)
{
    asm volatile(
        "mma.sync.aligned.m16n8k8.row.col.f32.tf32.tf32.f32 "
        "{%0,%1,%2,%3}, {%4,%5,%6,%7}, {%8,%9}, {%0,%1,%2,%3};"
        : "+f"(d[0]), "+f"(d[1]), "+f"(d[2]), "+f"(d[3])
        : "r"(a[0]), "r"(a[1]), "r"(a[2]), "r"(a[3]), "r"(b[0]), "r"(b[1]));
}
static __device__ __forceinline__ uint32_t ld_u32(const float* p) {
    return __float_as_uint(*p);
}

// ============================================================================
// tf32 rounding pre-pass: out[i] = round_to_nearest_tf32(in[i])
// ============================================================================
__global__ void __launch_bounds__(256) round_tf32(const float* __restrict__ in,
                                                  float* __restrict__ out, int n4)
{
    int i = blockIdx.x * 256 + threadIdx.x;
    if (i >= n4) return;
    float4 v = ((const float4*)in)[i];
    float4 r;
    r.x = __uint_as_float(f2tf(v.x));
    r.y = __uint_as_float(f2tf(v.y));
    r.z = __uint_as_float(f2tf(v.z));
    r.w = __uint_as_float(f2tf(v.w));
    ((float4*)out)[i] = r;
}

// ============================================================================
// tf32 mma.sync GEMM NT:  C[m][n] = round_tf32( sum_k A[m][k] * W[n][k] )
// Inputs pre-rounded to tf32 -> NO cvt in the mainloop.
// CTA 128x128, BK=32, 256 threads (8 warps), warp tile 64x32.
// ============================================================================
#define SM_STRIDE 36
#define ABUF_F (128 * SM_STRIDE)

__global__ void __launch_bounds__(256) gemm_mma()
{
    extern __shared__ __align__(16) float sm[];
    const int tid  = threadIdx.x;
    const int lane = tid & 31;
    const int wid  = tid >> 5;
    const int g    = lane >> 2;
    const int tg   = lane & 3;
    const int wM   = wid >> 2;
    const int wN   = wid & 3;
    const int n0   = blockIdx.x * 128;
    const int m0   = blockIdx.y * 128;
    const int z    = blockIdx.z;

    const float* __restrict__ A = (z == 0) ? gAQ : gAK;
    const float* __restrict__ W = gWR + (size_t)z * DM * DM;
    float* __restrict__ C = (z == 0) ? gQ : ((z == 1) ? gK : gV);

    float* As[2] = { sm,              sm + ABUF_F };
    float* Bs[2] = { sm + 2 * ABUF_F, sm + 3 * ABUF_F };
    const uint32_t asA[2] = { smem_u32(As[0]), smem_u32(As[1]) };
    const uint32_t asB[2] = { smem_u32(Bs[0]), smem_u32(Bs[1]) };

    float acc[4][4][4] = {};

    const int lr  = tid >> 3;
    const int lc4 = tid & 7;

    {
        #pragma unroll
        for (int it = 0; it < 4; ++it) {
            int r = lr + it * 32;
            uint32_t da = asA[0] + (uint32_t)(r * SM_STRIDE + lc4 * 4) * 4u;
            const float* sa = A + (size_t)(m0 + r) * DM + lc4 * 4;
            asm volatile("cp.async.cg.shared.global [%0], [%1], 16;"
                         :: "r"(da), "l"(sa));
            uint32_t db = asB[0] + (uint32_t)(r * SM_STRIDE + lc4 * 4) * 4u;
            const float* sb = W + (size_t)(n0 + r) * DM + lc4 * 4;
            asm volatile("cp.async.cg.shared.global [%0], [%1], 16;"
                         :: "r"(db), "l"(sb));
        }
        asm volatile("cp.async.commit_group;" ::: "memory");
    }

    const int NSTAGE = DM / 32;
    for (int s = 0; s < NSTAGE; ++s) {
        const int buf = s & 1;
        if (s + 1 < NSTAGE) {
            const int nb = buf ^ 1;
            const int k0 = (s + 1) * 32;
            #pragma unroll
            for (int it = 0; it < 4; ++it) {
                int r = lr + it * 32;
                uint32_t da = asA[nb] + (uint32_t)(r * SM_STRIDE + lc4 * 4) * 4u;
                const float* sa = A + (size_t)(m0 + r) * DM + k0 + lc4 * 4;
                asm volatile("cp.async.cg.shared.global [%0], [%1], 16;"
                             :: "r"(da), "l"(sa));
                uint32_t db = asB[nb] + (uint32_t)(r * SM_STRIDE + lc4 * 4) * 4u;
                const float* sb = W + (size_t)(n0 + r) * DM + k0 + lc4 * 4;
                asm volatile("cp.async.cg.shared.global [%0], [%1], 16;"
                             :: "r"(db), "l"(sb));
            }
            asm volatile("cp.async.commit_group;" ::: "memory");
            asm volatile("cp.async.wait_group %0;" :: "n"(1) : "memory");
        } else {
            asm volatile("cp.async.wait_group %0;" :: "n"(0) : "memory");
        }
        __syncthreads();

        const float* pa = As[buf];
        const float* pb = Bs[buf];
        #pragma unroll
        for (int kk = 0; kk < 4; ++kk) {
            const int kb = kk * 8;
            uint32_t af[4][4];
            #pragma unroll
            for (int mt = 0; mt < 4; ++mt) {
                int row = wM * 64 + mt * 16 + g;
                const float* base = pa + row * SM_STRIDE + kb + tg;
                af[mt][0] = ld_u32(base);
                af[mt][1] = ld_u32(base + 8 * SM_STRIDE);
                af[mt][2] = ld_u32(base + 4);
                af[mt][3] = ld_u32(base + 8 * SM_STRIDE + 4);
            }
            uint32_t bf[4][2];
            #pragma unroll
            for (int nt = 0; nt < 4; ++nt) {
                int nn = wN * 32 + nt * 8 + g;
                const float* base = pb + nn * SM_STRIDE + kb + tg;
                bf[nt][0] = ld_u32(base);
                bf[nt][1] = ld_u32(base + 4);
            }
            #pragma unroll
            for (int mt = 0; mt < 4; ++mt)
                #pragma unroll
                for (int nt = 0; nt < 4; ++nt)
                    mma_tf32(acc[mt][nt], af[mt], bf[nt]);
        }
        __syncthreads();
    }

    // Epilogue: store tf32-ROUNDED results (downstream mma reads them raw).
    #pragma unroll
    for (int mt = 0; mt < 4; ++mt) {
        int row = m0 + wM * 64 + mt * 16 + g;
        #pragma unroll
        for (int nt = 0; nt < 4; ++nt) {
            int col = n0 + wN * 32 + nt * 8 + tg * 2;
            float2 v0, v1;
            v0.x = __uint_as_float(f2tf(acc[mt][nt][0]));
            v0.y = __uint_as_float(f2tf(acc[mt][nt][1]));
            v1.x = __uint_as_float(f2tf(acc[mt][nt][2]));
            v1.y = __uint_as_float(f2tf(acc[mt][nt][3]));
            *(float2*)(C + (size_t)row * DM + col) = v0;
            *(float2*)(C + (size_t)(row + 8) * DM + col) = v1;
        }
    }
}

// ============================================================================
// tf32 mma.sync causal flash attention (unchanged from R6 best structure).
// ============================================================================
#define SW(r, c) (((r) << 6) + ((c) ^ (((r) & 7) << 3)))

__global__ void __launch_bounds__(128) attn_mma(const float* __restrict__ query)
{
    extern __shared__ __align__(16) float sm[];
    float* Kb[2] = { sm,           sm + 8192 };
    float* Vb[2] = { sm + 4096,    sm + 12288 };
    float* Ss    = sm + 16384;
    const uint32_t sK[2] = { smem_u32(Kb[0]), smem_u32(Kb[1]) };
    const uint32_t sV[2] = { smem_u32(Vb[0]), smem_u32(Vb[1]) };

    const int tid  = threadIdx.x;
    const int lane = tid & 31;
    const int wid  = tid >> 5;
    const int g    = lane >> 2;
    const int tg   = lane & 3;
    const int qt   = (int)(gridDim.x - 1) - (int)blockIdx.x;  // heavy-first
    const int h    = blockIdx.y;
    const int n    = blockIdx.z;

    const size_t nbase = (size_t)n * LQL * DM;
    const int hcol = h * PP;
    const int KT = 2 * qt + 2;

    {
        const float* Kg = gK + nbase + hcol;
        const float* Vg = gV + nbase + hcol;
        #pragma unroll
        for (int i = 0; i < 8; ++i) {
            int idx = tid + i * 128;
            int r = idx >> 4, c = (idx & 15) << 2;
            uint32_t dst = (uint32_t)SW(r, c) * 4u;
            asm volatile("cp.async.cg.shared.global [%0], [%1], 16;"
                         :: "r"(sK[0] + dst), "l"(Kg + (size_t)r * DM + c));
            asm volatile("cp.async.cg.shared.global [%0], [%1], 16;"
                         :: "r"(sV[0] + dst), "l"(Vg + (size_t)r * DM + c));
        }
        asm volatile("cp.async.commit_group;" ::: "memory");
    }

    {
        const float* Qg = gQ + nbase + (size_t)qt * 128 * DM + hcol;
        #pragma unroll
        for (int i = 0; i < 16; ++i) {
            int idx = tid + i * 128;
            int r = idx >> 4, c = (idx & 15) << 2;
            float4 v = *(const float4*)(Qg + (size_t)r * DM + c);
            *(float4*)(Ss + SW(r, c)) = v;
        }
    }
    __syncthreads();
    uint32_t qf[2][8][4];
    #pragma unroll
    for (int mb = 0; mb < 2; ++mb) {
        int r0 = wid * 32 + mb * 16 + g;
        #pragma unroll
        for (int ks = 0; ks < 8; ++ks) {
            qf[mb][ks][0] = ld_u32(Ss + SW(r0,     ks * 8 + tg));
            qf[mb][ks][1] = ld_u32(Ss + SW(r0 + 8, ks * 8 + tg));
            qf[mb][ks][2] = ld_u32(Ss + SW(r0,     ks * 8 + tg + 4));
            qf[mb][ks][3] = ld_u32(Ss + SW(r0 + 8, ks * 8 + tg + 4));
        }
    }
    __syncthreads();

    float o[2][8][4] = {};
    float mrow[2][2], lrow[2][2];
    #pragma unroll
    for (int a = 0; a < 2; ++a)
        #pragma unroll
        for (int b = 0; b < 2; ++b) { mrow[a][b] = -INFINITY; lrow[a][b] = 0.f; }

    for (int kt = 0; kt < KT; ++kt) {
        const int buf = kt & 1;
        if (kt + 1 < KT) {
            const float* Kg = gK + nbase + (size_t)(kt + 1) * 64 * DM + hcol;
            const float* Vg = gV + nbase + (size_t)(kt + 1) * 64 * DM + hcol;
            #pragma unroll
            for (int i = 0; i < 8; ++i) {
                int idx = tid + i * 128;
                int r = idx >> 4, c = (idx & 15) << 2;
                uint32_t dst = (uint32_t)SW(r, c) * 4u;
                asm volatile("cp.async.cg.shared.global [%0], [%1], 16;"
                             :: "r"(sK[buf ^ 1] + dst), "l"(Kg + (size_t)r * DM + c));
                asm volatile("cp.async.cg.shared.global [%0], [%1], 16;"
                             :: "r"(sV[buf ^ 1] + dst), "l"(Vg + (size_t)r * DM + c));
            }
            asm volatile("cp.async.commit_group;" ::: "memory");
            asm volatile("cp.async.wait_group %0;" :: "n"(1) : "memory");
        } else {
            asm volatile("cp.async.wait_group %0;" :: "n"(0) : "memory");
        }
        __syncthreads();

        const float* Ks = Kb[buf];
        const float* Vs = Vb[buf];

        float s[2][8][4] = {};
        #pragma unroll
        for (int ks = 0; ks < 8; ++ks) {
            #pragma unroll
            for (int nb = 0; nb < 8; ++nb) {
                uint32_t bb[2];
                bb[0] = ld_u32(Ks + SW(nb * 8 + g, ks * 8 + tg));
                bb[1] = ld_u32(Ks + SW(nb * 8 + g, ks * 8 + tg + 4));
                mma_tf32(s[0][nb], qf[0][ks], bb);
                mma_tf32(s[1][nb], qf[1][ks], bb);
            }
        }

        const bool tail = (kt >= 2 * qt);
        #pragma unroll
        for (int mb = 0; mb < 2; ++mb) {
            #pragma unroll
            for (int rr = 0; rr < 2; ++rr) {
                const int grow = qt * 128 + wid * 32 + mb * 16 + rr * 8 + g;
                float tm = -INFINITY;
                #pragma unroll
                for (int nb = 0; nb < 8; ++nb) {
                    float v0 = s[mb][nb][rr * 2 + 0] * 0.03125f;
                    float v1 = s[mb][nb][rr * 2 + 1] * 0.03125f;
                    if (tail) {
                        int c0 = kt * 64 + nb * 8 + tg * 2;
                        if (c0     > grow) v0 = -1e30f;
                        if (c0 + 1 > grow) v1 = -1e30f;
                    }
                    s[mb][nb][rr * 2 + 0] = v0;
                    s[mb][nb][rr * 2 + 1] = v1;
                    tm = fmaxf(tm, fmaxf(v0, v1));
                }
                tm = fmaxf(tm, __shfl_xor_sync(0xffffffffu, tm, 1));
                tm = fmaxf(tm, __shfl_xor_sync(0xffffffffu, tm, 2));
                float nm   = fmaxf(mrow[mb][rr], tm);
                float corr = __expf(mrow[mb][rr] - nm);
                mrow[mb][rr] = nm;
                float rs = 0.f;
                #pragma unroll
                for (int nb = 0; nb < 8; ++nb) {
                    float p0 = __expf(s[mb][nb][rr * 2 + 0] - nm);
                    float p1 = __expf(s[mb][nb][rr * 2 + 1] - nm);
                    s[mb][nb][rr * 2 + 0] = p0;
                    s[mb][nb][rr * 2 + 1] = p1;
                    rs += p0 + p1;
                }
                rs += __shfl_xor_sync(0xffffffffu, rs, 1);
                rs += __shfl_xor_sync(0xffffffffu, rs, 2);
                lrow[mb][rr] = lrow[mb][rr] * corr + rs;
                #pragma unroll
                for (int nb = 0; nb < 8; ++nb) {
                    o[mb][nb][rr * 2 + 0] *= corr;
                    o[mb][nb][rr * 2 + 1] *= corr;
                }
            }
        }

        #pragma unroll
        for (int mb = 0; mb < 2; ++mb) {
            int r0 = wid * 32 + mb * 16 + g;
            #pragma unroll
            for (int nb = 0; nb < 8; ++nb) {
                float2 w0, w1;
                w0.x = __uint_as_float(f2tf(s[mb][nb][0]));
                w0.y = __uint_as_float(f2tf(s[mb][nb][1]));
                w1.x = __uint_as_float(f2tf(s[mb][nb][2]));
                w1.y = __uint_as_float(f2tf(s[mb][nb][3]));
                *(float2*)(Ss + SW(r0,     nb * 8 + tg * 2)) = w0;
                *(float2*)(Ss + SW(r0 + 8, nb * 8 + tg * 2)) = w1;
            }
        }

        #pragma unroll
        for (int ks = 0; ks < 8; ++ks) {
            uint32_t af[2][4];
            #pragma unroll
            for (int mb = 0; mb < 2; ++mb) {
                int r0 = wid * 32 + mb * 16 + g;
                af[mb][0] = ld_u32(Ss + SW(r0,     ks * 8 + tg));
                af[mb][1] = ld_u32(Ss + SW(r0 + 8, ks * 8 + tg));
                af[mb][2] = ld_u32(Ss + SW(r0,     ks * 8 + tg + 4));
                af[mb][3] = ld_u32(Ss + SW(r0 + 8, ks * 8 + tg + 4));
            }
            #pragma unroll
            for (int nb = 0; nb < 8; ++nb) {
                uint32_t bb[2];
                bb[0] = ld_u32(Vs + SW(ks * 8 + tg,     nb * 8 + g));
                bb[1] = ld_u32(Vs + SW(ks * 8 + tg + 4, nb * 8 + g));
                mma_tf32(o[0][nb], af[0], bb);
                mma_tf32(o[1][nb], af[1], bb);
            }
        }
        __syncthreads();   // WAR: next prefetch overwrites the buffer just read
    }

    #pragma unroll
    for (int mb = 0; mb < 2; ++mb) {
        #pragma unroll
        for (int rr = 0; rr < 2; ++rr) {
            float inv = 1.0f / lrow[mb][rr];
            int grow = qt * 128 + wid * 32 + mb * 16 + rr * 8 + g;
            size_t rowoff = nbase + (size_t)grow * DM + hcol;
            #pragma unroll
            for (int nb = 0; nb < 8; ++nb) {
                int c = nb * 8 + tg * 2;
                float2 qv = *(const float2*)(query + rowoff + c);
                float2 w;
                w.x = o[mb][nb][rr * 2 + 0] * inv + qv.x;
                w.y = o[mb][nb][rr * 2 + 1] * inv + qv.y;
                *(float2*)(gRes + rowoff + c) = w;
            }
        }
    }
}

// ---------------------------------------------------------------------------
// BatchNorm: deterministic two-stage column stats + fused normalize
// ---------------------------------------------------------------------------
__global__ void __launch_bounds__(256) colstats_partial()
{
    const int col   = blockIdx.x * 256 + threadIdx.x;
    const int chunk = blockIdx.y;
    const float* base = gRes + (size_t)chunk * 128 * DM + col;
    float s = 0.f, q = 0.f;
    #pragma unroll 8
    for (int r = 0; r < 128; ++r) {
        float v = base[(size_t)r * DM];
        s += v;
        q += v * v;
    }
    gPartS[chunk * DM + col] = s;
    gPartQ[chunk * DM + col] = q;
}

__global__ void __launch_bounds__(256) colstats_final(const float* __restrict__ gamma,
                                                      const float* __restrict__ beta)
{
    const int cidx = threadIdx.x & 31;
    const int seg  = threadIdx.x >> 5;
    const int col  = blockIdx.x * 32 + cidx;
    float s = 0.f, q = 0.f;
    #pragma unroll
    for (int c = 0; c < 8; ++c) {
        int chunk = seg * 8 + c;
        s += gPartS[chunk * DM + col];
        q += gPartQ[chunk * DM + col];
    }
    __shared__ float shS[8][33], shQ[8][33];
    shS[seg][cidx] = s;
    shQ[seg][cidx] = q;
    __syncthreads();
    if (seg == 0) {
        float ts = 0.f, tq = 0.f;
        #pragma unroll
        for (int i = 0; i < 8; ++i) { ts += shS[i][cidx]; tq += shQ[i][cidx]; }
        const float invn = 1.0f / (float)MROWS;
        float mean = ts * invn;
        float var  = tq * invn - mean * mean;
        float inv  = rsqrtf(var + EPSBN);
        float a    = gamma[col] * inv;
        gColA[col] = a;
        gColB[col] = beta[col] - mean * a;
    }
}

__global__ void __launch_bounds__(256) normalize_kernel(float* __restrict__ out)
{
    const size_t idx = (size_t)blockIdx.x * 256 + threadIdx.x;
    float4 v = ((const float4*)gRes)[idx];
    int col = (int)((idx * 4) & (DM - 1));
    float4 r;
    r.x = v.x * gColA[col + 0] + gColB[col + 0];
    r.y = v.y * gColA[col + 1] + gColB[col + 1];
    r.z = v.z * gColA[col + 2] + gColB[col + 2];
    r.w = v.w * gColA[col + 3] + gColB[col + 3];
    ((float4*)out)[idx] = r;
}

// ---------------------------------------------------------------------------
extern "C" void kernel_launch(void* const* d_in, const int* in_sizes, int n_in,
                              void* d_out, int out_size)
{
    const float* query = (const float*)d_in[0];
    const float* key   = (const float*)d_in[1];
    const float* Wq    = (const float*)d_in[2];
    const float* Wk    = (const float*)d_in[3];
    const float* Wv    = (const float*)d_in[4];
    const float* gamma = (const float*)d_in[5];
    const float* beta  = (const float*)d_in[6];
    float* out = (float*)d_out;

    float *pAQ, *pAK, *pWR;
    cudaGetSymbolAddress((void**)&pAQ, gAQ);
    cudaGetSymbolAddress((void**)&pAK, gAK);
    cudaGetSymbolAddress((void**)&pWR, gWR);

    // tf32 round-to-nearest pre-pass (moves all cvt out of the GEMM mainloop)
    const int n4_act = MROWS * DM / 4;
    const int n4_w   = DM * DM / 4;
    round_tf32<<<n4_act / 256, 256>>>(query, pAQ, n4_act);
    round_tf32<<<n4_act / 256, 256>>>(key,   pAK, n4_act);
    round_tf32<<<n4_w / 256, 256>>>(Wq, pWR,               n4_w);
    round_tf32<<<n4_w / 256, 256>>>(Wk, pWR + DM * DM,     n4_w);
    round_tf32<<<n4_w / 256, 256>>>(Wv, pWR + 2 * DM * DM, n4_w);

    const int gemm_smem = 4 * ABUF_F * 4;    // 73728
    cudaFuncSetAttribute(gemm_mma, cudaFuncAttributeMaxDynamicSharedMemorySize,
                         gemm_smem);
    dim3 gg(DM / 128, MROWS / 128, 3);
    gemm_mma<<<gg, 256, gemm_smem>>>();

    const int attn_smem = 24576 * 4;         // 96KB
    cudaFuncSetAttribute(attn_mma, cudaFuncAttributeMaxDynamicSharedMemorySize,
                         attn_smem);
    dim3 ga(LQL / 128, HH, NB);
    attn_mma<<<ga, 128, attn_smem>>>(query);

    colstats_partial<<<dim3(DM / 256, 64), 256>>>();
    colstats_final<<<DM / 32, 256>>>(gamma, beta);

    const int total_f4 = MROWS * DM / 4;
    normalize_kernel<<<total_f4 / 256, 256>>>(out);
}

// round 8
// speedup vs baseline: 1.6909x; 1.6909x over previous
#include <cuda_runtime.h>
#include <cuda_fp16.h>
#include <math.h>
#include <stdint.h>

// Problem constants (fixed shapes)
#define NB   4
#define LQL  2048
#define DM   1024
#define HH   16
#define PP   64
#define MROWS (NB*LQL)        // 8192
#define EPSBN 1e-5f

// ---------------- scratch (device globals: allocation-free) ----------------
__device__ __half gQh [MROWS * DM];   // fp16 Q projection
__device__ __half gKh [MROWS * DM];   // fp16 K projection
__device__ __half gVh [MROWS * DM];   // fp16 V projection
__device__ __half gAQh[MROWS * DM];   // fp16 query (GEMM A)
__device__ __half gAKh[MROWS * DM];   // fp16 key   (GEMM A)
__device__ __half gWh [3 * DM * DM];  // fp16 Wq,Wk,Wv (GEMM B)
__device__ float  gRes[MROWS * DM];
__device__ float  gPartS[64 * DM];
__device__ float  gPartQ[64 * DM];
__device__ float  gColA[DM];
__device__ float  gColB[DM];

// ---------------- helpers ----------------
static __device__ __forceinline__ uint32_t smem_u32(const void* p) {
    uint32_t r;
    asm("{ .reg .u64 t; cvta.to.shared.u64 t, %1; cvt.u32.u64 %0, t; }"
        : "=r"(r) : "l"(p));
    return r;
}
static __device__ __forceinline__ uint32_t ld32h(const __half* p) {
    return *(const uint32_t*)p;
}
static __device__ __forceinline__ void mma_f16(float* d, const uint32_t* a,
                                               uint32_t b0, uint32_t b1)
{
    asm volatile(
        "mma.sync.aligned.m16n8k16.row.col.f32.f16.f16.f32 "
        "{%0,%1,%2,%3}, {%4,%5,%6,%7}, {%8,%9}, {%0,%1,%2,%3};"
        : "+f"(d[0]), "+f"(d[1]), "+f"(d[2]), "+f"(d[3])
        : "r"(a[0]), "r"(a[1]), "r"(a[2]), "r"(a[3]), "r"(b0), "r"(b1));
}
static __device__ __forceinline__ void ldsm_x2_t(uint32_t& r0, uint32_t& r1,
                                                 uint32_t addr)
{
    asm volatile("ldmatrix.sync.aligned.m8n8.x2.trans.shared.b16 {%0,%1}, [%2];"
                 : "=r"(r0), "=r"(r1) : "r"(addr));
}
// swizzled half-index within a tile of 64-half (128B) rows
#define SWH(r, hc) (((r) << 6) + (((hc) & 7) | ((((hc) >> 3) ^ ((r) & 7)) << 3)))

// ============================================================================
// f32 -> f16 conversion pre-pass
// ============================================================================
__global__ void __launch_bounds__(256) conv_f16(const float* __restrict__ in,
                                                __half* __restrict__ out, int n4)
{
    int i = blockIdx.x * 256 + threadIdx.x;
    if (i >= n4) return;
    float4 v = ((const float4*)in)[i];
    __half2* o = (__half2*)out + 2 * (size_t)i;
    o[0] = __floats2half2_rn(v.x, v.y);
    o[1] = __floats2half2_rn(v.z, v.w);
}

// ============================================================================
// fp16 mma.sync GEMM NT: C[m][n] = f16( sum_k A[m][k] * W[n][k] )
// CTA 128x128, BK=64 halves, 256 threads (8 warps), warp tile 64x32,
// m16n8k16, cp.async double-buffered, XOR-swizzled smem.
// ============================================================================
#define GSTG 8192   // halves per stage per matrix (128 rows x 64 halves)

__global__ void __launch_bounds__(256) gemm_mma()
{
    extern __shared__ __align__(16) __half smh[];
    const int tid  = threadIdx.x;
    const int lane = tid & 31;
    const int wid  = tid >> 5;
    const int g    = lane >> 2;
    const int tg   = lane & 3;
    const int wM   = wid >> 2;
    const int wN   = wid & 3;
    const int n0   = blockIdx.x * 128;
    const int m0   = blockIdx.y * 128;
    const int z    = blockIdx.z;

    const __half* __restrict__ A = (z == 0) ? gAQh : gAKh;
    const __half* __restrict__ W = gWh + (size_t)z * DM * DM;
    __half* __restrict__ C = (z == 0) ? gQh : ((z == 1) ? gKh : gVh);

    __half* As[2] = { smh,            smh + GSTG };
    __half* Bs[2] = { smh + 2 * GSTG, smh + 3 * GSTG };
    const uint32_t asA[2] = { smem_u32(As[0]), smem_u32(As[1]) };
    const uint32_t asB[2] = { smem_u32(Bs[0]), smem_u32(Bs[1]) };

    float acc[4][4][4] = {};

    // load mapping: 1024 16B-chunks per matrix-stage; 256 threads x 4 iters
    const int lr  = tid >> 3;    // row base 0..31
    const int lc8 = tid & 7;     // 16B chunk 0..7

    {
        #pragma unroll
        for (int it = 0; it < 4; ++it) {
            int r = lr + it * 32;
            uint32_t off = (uint32_t)(r * 128 + ((lc8 ^ (r & 7)) << 4));
            const __half* sa = A + (size_t)(m0 + r) * DM + lc8 * 8;
            asm volatile("cp.async.cg.shared.global [%0], [%1], 16;"
                         :: "r"(asA[0] + off), "l"(sa));
            const __half* sb = W + (size_t)(n0 + r) * DM + lc8 * 8;
            asm volatile("cp.async.cg.shared.global [%0], [%1], 16;"
                         :: "r"(asB[0] + off), "l"(sb));
        }
        asm volatile("cp.async.commit_group;" ::: "memory");
    }

    const int NSTAGE = DM / 64;   // 16
    for (int s = 0; s < NSTAGE; ++s) {
        const int buf = s & 1;
        if (s + 1 < NSTAGE) {
            const int nb = buf ^ 1;
            const int k0 = (s + 1) * 64;
            #pragma unroll
            for (int it = 0; it < 4; ++it) {
                int r = lr + it * 32;
                uint32_t off = (uint32_t)(r * 128 + ((lc8 ^ (r & 7)) << 4));
                const __half* sa = A + (size_t)(m0 + r) * DM + k0 + lc8 * 8;
                asm volatile("cp.async.cg.shared.global [%0], [%1], 16;"
                             :: "r"(asA[nb] + off), "l"(sa));
                const __half* sb = W + (size_t)(n0 + r) * DM + k0 + lc8 * 8;
                asm volatile("cp.async.cg.shared.global [%0], [%1], 16;"
                             :: "r"(asB[nb] + off), "l"(sb));
            }
            asm volatile("cp.async.commit_group;" ::: "memory");
            asm volatile("cp.async.wait_group %0;" :: "n"(1) : "memory");
        } else {
            asm volatile("cp.async.wait_group %0;" :: "n"(0) : "memory");
        }
        __syncthreads();

        const __half* pa = As[buf];
        const __half* pb = Bs[buf];
        #pragma unroll
        for (int kk = 0; kk < 4; ++kk) {          // 4 x k16 = 64
            const int kb = kk * 16;
            uint32_t af[4][4];
            #pragma unroll
            for (int mt = 0; mt < 4; ++mt) {
                int row = wM * 64 + mt * 16 + g;
                af[mt][0] = ld32h(pa + SWH(row,     kb + 2 * tg));
                af[mt][1] = ld32h(pa + SWH(row + 8, kb + 2 * tg));
                af[mt][2] = ld32h(pa + SWH(row,     kb + 2 * tg + 8));
                af[mt][3] = ld32h(pa + SWH(row + 8, kb + 2 * tg + 8));
            }
            uint32_t bf[4][2];
            #pragma unroll
            for (int nt = 0; nt < 4; ++nt) {
                int nn = wN * 32 + nt * 8 + g;
                bf[nt][0] = ld32h(pb + SWH(nn, kb + 2 * tg));
                bf[nt][1] = ld32h(pb + SWH(nn, kb + 2 * tg + 8));
            }
            #pragma unroll
            for (int mt = 0; mt < 4; ++mt)
                #pragma unroll
                for (int nt = 0; nt < 4; ++nt)
                    mma_f16(acc[mt][nt], af[mt], bf[nt][0], bf[nt][1]);
        }
        __syncthreads();
    }

    // Epilogue: fp16 store
    #pragma unroll
    for (int mt = 0; mt < 4; ++mt) {
        int row = m0 + wM * 64 + mt * 16 + g;
        #pragma unroll
        for (int nt = 0; nt < 4; ++nt) {
            int col = n0 + wN * 32 + nt * 8 + tg * 2;
            *(__half2*)(C + (size_t)row * DM + col) =
                __floats2half2_rn(acc[mt][nt][0], acc[mt][nt][1]);
            *(__half2*)(C + (size_t)(row + 8) * DM + col) =
                __floats2half2_rn(acc[mt][nt][2], acc[mt][nt][3]);
        }
    }
}

// ============================================================================
// fp16 mma.sync causal flash attention.
// Q-tile 128x64, 4 warps, K/V 64x64 fp16 tiles double-buffered (8KB each),
// P in fp16 smem, PV B-operand via ldmatrix.x2.trans. Smem 48KB.
// ============================================================================
__global__ void __launch_bounds__(128) attn_mma(const float* __restrict__ query)
{
    extern __shared__ __align__(16) __half ash[];
    __half* Kb[2] = { ash,         ash + 8192 };
    __half* Vb[2] = { ash + 4096,  ash + 12288 };
    __half* Ss    = ash + 16384;                 // 128 x 64 halves
    const uint32_t sK[2] = { smem_u32(Kb[0]), smem_u32(Kb[1]) };
    const uint32_t sV[2] = { smem_u32(Vb[0]), smem_u32(Vb[1]) };

    const int tid  = threadIdx.x;
    const int lane = tid & 31;
    const int wid  = tid >> 5;
    const int g    = lane >> 2;
    const int tg   = lane & 3;
    const int qt   = (int)(gridDim.x - 1) - (int)blockIdx.x;  // heavy-first
    const int h    = blockIdx.y;
    const int n    = blockIdx.z;

    const size_t nbase = (size_t)n * LQL * DM;
    const int hcol = h * PP;
    const int KT = 2 * qt + 2;

    // ---- prefetch K/V tile 0 (64 rows x 64 halves = 512 16B chunks each) ----
    {
        const __half* Kg = gKh + nbase + hcol;
        const __half* Vg = gVh + nbase + hcol;
        #pragma unroll
        for (int i = 0; i < 4; ++i) {
            int idx = tid + i * 128;
            int r = idx >> 3, c8 = idx & 7;
            uint32_t off = (uint32_t)(r * 128 + ((c8 ^ (r & 7)) << 4));
            asm volatile("cp.async.cg.shared.global [%0], [%1], 16;"
                         :: "r"(sK[0] + off), "l"(Kg + (size_t)r * DM + c8 * 8));
            asm volatile("cp.async.cg.shared.global [%0], [%1], 16;"
                         :: "r"(sV[0] + off), "l"(Vg + (size_t)r * DM + c8 * 8));
        }
        asm volatile("cp.async.commit_group;" ::: "memory");
    }

    // ---- stage Q tile (128x64 halves) into Ss, load register fragments ----
    {
        const __half* Qg = gQh + nbase + (size_t)qt * 128 * DM + hcol;
        #pragma unroll
        for (int i = 0; i < 8; ++i) {
            int idx = tid + i * 128;
            int r = idx >> 3, c8 = idx & 7;
            uint4 v = *(const uint4*)(Qg + (size_t)r * DM + c8 * 8);
            *(uint4*)(Ss + SWH(r, c8 * 8)) = v;
        }
    }
    __syncthreads();
    uint32_t qf[2][4][4];
    #pragma unroll
    for (int mb = 0; mb < 2; ++mb) {
        int r0 = wid * 32 + mb * 16 + g;
        #pragma unroll
        for (int ks = 0; ks < 4; ++ks) {
            const int kb = ks * 16;
            qf[mb][ks][0] = ld32h(Ss + SWH(r0,     kb + 2 * tg));
            qf[mb][ks][1] = ld32h(Ss + SWH(r0 + 8, kb + 2 * tg));
            qf[mb][ks][2] = ld32h(Ss + SWH(r0,     kb + 2 * tg + 8));
            qf[mb][ks][3] = ld32h(Ss + SWH(r0 + 8, kb + 2 * tg + 8));
        }
    }
    __syncthreads();

    float o[2][8][4] = {};
    float mrow[2][2], lrow[2][2];
    #pragma unroll
    for (int a = 0; a < 2; ++a)
        #pragma unroll
        for (int b = 0; b < 2; ++b) { mrow[a][b] = -INFINITY; lrow[a][b] = 0.f; }

    for (int kt = 0; kt < KT; ++kt) {
        const int buf = kt & 1;
        if (kt + 1 < KT) {
            const __half* Kg = gKh + nbase + (size_t)(kt + 1) * 64 * DM + hcol;
            const __half* Vg = gVh + nbase + (size_t)(kt + 1) * 64 * DM + hcol;
            #pragma unroll
            for (int i = 0; i < 4; ++i) {
                int idx = tid + i * 128;
                int r = idx >> 3, c8 = idx & 7;
                uint32_t off = (uint32_t)(r * 128 + ((c8 ^ (r & 7)) << 4));
                asm volatile("cp.async.cg.shared.global [%0], [%1], 16;"
                             :: "r"(sK[buf ^ 1] + off), "l"(Kg + (size_t)r * DM + c8 * 8));
                asm volatile("cp.async.cg.shared.global [%0], [%1], 16;"
                             :: "r"(sV[buf ^ 1] + off), "l"(Vg + (size_t)r * DM + c8 * 8));
            }
            asm volatile("cp.async.commit_group;" ::: "memory");
            asm volatile("cp.async.wait_group %0;" :: "n"(1) : "memory");
        } else {
            asm volatile("cp.async.wait_group %0;" :: "n"(0) : "memory");
        }
        __syncthreads();

        const __half* Ks = Kb[buf];

        // ---- S = Q K^T ----
        float s[2][8][4] = {};
        #pragma unroll
        for (int ks = 0; ks < 4; ++ks) {
            const int kb = ks * 16;
            #pragma unroll
            for (int nb = 0; nb < 8; ++nb) {
                int kr = nb * 8 + g;
                uint32_t b0 = ld32h(Ks + SWH(kr, kb + 2 * tg));
                uint32_t b1 = ld32h(Ks + SWH(kr, kb + 2 * tg + 8));
                mma_f16(s[0][nb], qf[0][ks], b0, b1);
                mma_f16(s[1][nb], qf[1][ks], b0, b1);
            }
        }

        // ---- mask + online softmax ----
        const bool tail = (kt >= 2 * qt);
        #pragma unroll
        for (int mb = 0; mb < 2; ++mb) {
            #pragma unroll
            for (int rr = 0; rr < 2; ++rr) {
                const int grow = qt * 128 + wid * 32 + mb * 16 + rr * 8 + g;
                float tm = -INFINITY;
                #pragma unroll
                for (int nb = 0; nb < 8; ++nb) {
                    float v0 = s[mb][nb][rr * 2 + 0] * 0.03125f;
                    float v1 = s[mb][nb][rr * 2 + 1] * 0.03125f;
                    if (tail) {
                        int c0 = kt * 64 + nb * 8 + tg * 2;
                        if (c0     > grow) v0 = -1e30f;
                        if (c0 + 1 > grow) v1 = -1e30f;
                    }
                    s[mb][nb][rr * 2 + 0] = v0;
                    s[mb][nb][rr * 2 + 1] = v1;
                    tm = fmaxf(tm, fmaxf(v0, v1));
                }
                tm = fmaxf(tm, __shfl_xor_sync(0xffffffffu, tm, 1));
                tm = fmaxf(tm, __shfl_xor_sync(0xffffffffu, tm, 2));
                float nm   = fmaxf(mrow[mb][rr], tm);
                float corr = __expf(mrow[mb][rr] - nm);
                mrow[mb][rr] = nm;
                float rs = 0.f;
                #pragma unroll
                for (int nb = 0; nb < 8; ++nb) {
                    float p0 = __expf(s[mb][nb][rr * 2 + 0] - nm);
                    float p1 = __expf(s[mb][nb][rr * 2 + 1] - nm);
                    s[mb][nb][rr * 2 + 0] = p0;
                    s[mb][nb][rr * 2 + 1] = p1;
                    rs += p0 + p1;
                }
                rs += __shfl_xor_sync(0xffffffffu, rs, 1);
                rs += __shfl_xor_sync(0xffffffffu, rs, 2);
                lrow[mb][rr] = lrow[mb][rr] * corr + rs;
                #pragma unroll
                for (int nb = 0; nb < 8; ++nb) {
                    o[mb][nb][rr * 2 + 0] *= corr;
                    o[mb][nb][rr * 2 + 1] *= corr;
                }
            }
        }

        // ---- store P (fp16) to Ss (warp-private rows) ----
        #pragma unroll
        for (int mb = 0; mb < 2; ++mb) {
            int r0 = wid * 32 + mb * 16 + g;
            #pragma unroll
            for (int nb = 0; nb < 8; ++nb) {
                *(__half2*)(Ss + SWH(r0,     nb * 8 + 2 * tg)) =
                    __floats2half2_rn(s[mb][nb][0], s[mb][nb][1]);
                *(__half2*)(Ss + SWH(r0 + 8, nb * 8 + 2 * tg)) =
                    __floats2half2_rn(s[mb][nb][2], s[mb][nb][3]);
            }
        }

        // ---- O += P V  (V B-frags via ldmatrix.x2.trans) ----
        #pragma unroll
        for (int ks = 0; ks < 4; ++ks) {
            const int kb = ks * 16;
            uint32_t af[2][4];
            #pragma unroll
            for (int mb = 0; mb < 2; ++mb) {
                int r0 = wid * 32 + mb * 16 + g;
                af[mb][0] = ld32h(Ss + SWH(r0,     kb + 2 * tg));
                af[mb][1] = ld32h(Ss + SWH(r0 + 8, kb + 2 * tg));
                af[mb][2] = ld32h(Ss + SWH(r0,     kb + 2 * tg + 8));
                af[mb][3] = ld32h(Ss + SWH(r0 + 8, kb + 2 * tg + 8));
            }
            const int vrow = kb + (lane & 15);
            const uint32_t rowbase = sV[buf] + (uint32_t)vrow * 128u;
            const uint32_t rx = (uint32_t)(vrow & 7) << 4;
            #pragma unroll
            for (int nb = 0; nb < 8; ++nb) {
                uint32_t addr = rowbase + (((uint32_t)nb << 4) ^ rx);
                uint32_t b0, b1;
                ldsm_x2_t(b0, b1, addr);
                mma_f16(o[0][nb], af[0], b0, b1);
                mma_f16(o[1][nb], af[1], b0, b1);
            }
        }
        __syncthreads();   // WAR before next prefetch overwrites buffers
    }

    // ---- epilogue: normalize, add residual (fp32), write gRes ----
    #pragma unroll
    for (int mb = 0; mb < 2; ++mb) {
        #pragma unroll
        for (int rr = 0; rr < 2; ++rr) {
            float inv = 1.0f / lrow[mb][rr];
            int grow = qt * 128 + wid * 32 + mb * 16 + rr * 8 + g;
            size_t rowoff = nbase + (size_t)grow * DM + hcol;
            #pragma unroll
            for (int nb = 0; nb < 8; ++nb) {
                int c = nb * 8 + tg * 2;
                float2 qv = *(const float2*)(query + rowoff + c);
                float2 w;
                w.x = o[mb][nb][rr * 2 + 0] * inv + qv.x;
                w.y = o[mb][nb][rr * 2 + 1] * inv + qv.y;
                *(float2*)(gRes + rowoff + c) = w;
            }
        }
    }
}

// ---------------------------------------------------------------------------
// BatchNorm: deterministic two-stage column stats + fused normalize
// ---------------------------------------------------------------------------
__global__ void __launch_bounds__(256) colstats_partial()
{
    const int col   = blockIdx.x * 256 + threadIdx.x;
    const int chunk = blockIdx.y;
    const float* base = gRes + (size_t)chunk * 128 * DM + col;
    float s = 0.f, q = 0.f;
    #pragma unroll 8
    for (int r = 0; r < 128; ++r) {
        float v = base[(size_t)r * DM];
        s += v;
        q += v * v;
    }
    gPartS[chunk * DM + col] = s;
    gPartQ[chunk * DM + col] = q;
}

__global__ void __launch_bounds__(256) colstats_final(const float* __restrict__ gamma,
                                                      const float* __restrict__ beta)
{
    const int cidx = threadIdx.x & 31;
    const int seg  = threadIdx.x >> 5;
    const int col  = blockIdx.x * 32 + cidx;
    float s = 0.f, q = 0.f;
    #pragma unroll
    for (int c = 0; c < 8; ++c) {
        int chunk = seg * 8 + c;
        s += gPartS[chunk * DM + col];
        q += gPartQ[chunk * DM + col];
    }
    __shared__ float shS[8][33], shQ[8][33];
    shS[seg][cidx] = s;
    shQ[seg][cidx] = q;
    __syncthreads();
    if (seg == 0) {
        float ts = 0.f, tq = 0.f;
        #pragma unroll
        for (int i = 0; i < 8; ++i) { ts += shS[i][cidx]; tq += shQ[i][cidx]; }
        const float invn = 1.0f / (float)MROWS;
        float mean = ts * invn;
        float var  = tq * invn - mean * mean;
        float inv  = rsqrtf(var + EPSBN);
        float a    = gamma[col] * inv;
        gColA[col] = a;
        gColB[col] = beta[col] - mean * a;
    }
}

__global__ void __launch_bounds__(256) normalize_kernel(float* __restrict__ out)
{
    const size_t idx = (size_t)blockIdx.x * 256 + threadIdx.x;
    float4 v = ((const float4*)gRes)[idx];
    int col = (int)((idx * 4) & (DM - 1));
    float4 r;
    r.x = v.x * gColA[col + 0] + gColB[col + 0];
    r.y = v.y * gColA[col + 1] + gColB[col + 1];
    r.z = v.z * gColA[col + 2] + gColB[col + 2];
    r.w = v.w * gColA[col + 3] + gColB[col + 3];
    ((float4*)out)[idx] = r;
}

// ---------------------------------------------------------------------------
extern "C" void kernel_launch(void* const* d_in, const int* in_sizes, int n_in,
                              void* d_out, int out_size)
{
    const float* query = (const float*)d_in[0];
    const float* key   = (const float*)d_in[1];
    const float* Wq    = (const float*)d_in[2];
    const float* Wk    = (const float*)d_in[3];
    const float* Wv    = (const float*)d_in[4];
    const float* gamma = (const float*)d_in[5];
    const float* beta  = (const float*)d_in[6];
    float* out = (float*)d_out;

    __half *pAQ, *pAK, *pW;
    cudaGetSymbolAddress((void**)&pAQ, gAQh);
    cudaGetSymbolAddress((void**)&pAK, gAKh);
    cudaGetSymbolAddress((void**)&pW,  gWh);

    // fp16 conversion pre-pass
    const int n4_act = MROWS * DM / 4;
    const int n4_w   = DM * DM / 4;
    conv_f16<<<n4_act / 256, 256>>>(query, pAQ, n4_act);
    conv_f16<<<n4_act / 256, 256>>>(key,   pAK, n4_act);
    conv_f16<<<n4_w / 256, 256>>>(Wq, pW,               n4_w);
    conv_f16<<<n4_w / 256, 256>>>(Wk, pW + DM * DM,     n4_w);
    conv_f16<<<n4_w / 256, 256>>>(Wv, pW + 2 * DM * DM, n4_w);

    // fp16 projections
    const int gemm_smem = 4 * GSTG * 2;      // 65536 B
    cudaFuncSetAttribute(gemm_mma, cudaFuncAttributeMaxDynamicSharedMemorySize,
                         gemm_smem);
    dim3 gg(DM / 128, MROWS / 128, 3);
    gemm_mma<<<gg, 256, gemm_smem>>>();

    // fp16 flash attention
    const int attn_smem = 24576 * 2;         // 49152 B
    cudaFuncSetAttribute(attn_mma, cudaFuncAttributeMaxDynamicSharedMemorySize,
                         attn_smem);
    dim3 ga(LQL / 128, HH, NB);
    attn_mma<<<ga, 128, attn_smem>>>(query);

    colstats_partial<<<dim3(DM / 256, 64), 256>>>();
    colstats_final<<<DM / 32, 256>>>(gamma, beta);

    const int total_f4 = MROWS * DM / 4;
    normalize_kernel<<<total_f4 / 256, 256>>>(out);
}

// round 9
// speedup vs baseline: 2.0256x; 1.1980x over previous
#include <cuda_runtime.h>
#include <cuda_fp16.h>
#include <math.h>
#include <stdint.h>

// Problem constants (fixed shapes)
#define NB   4
#define LQL  2048
#define DM   1024
#define HH   16
#define PP   64
#define MROWS (NB*LQL)        // 8192
#define EPSBN 1e-5f

// ---------------- scratch (device globals: allocation-free) ----------------
__device__ __half gQh [MROWS * DM];   // fp16 Q projection
__device__ __half gKh [MROWS * DM];   // fp16 K projection
__device__ __half gVh [MROWS * DM];   // fp16 V projection
__device__ __half gAQh[MROWS * DM];   // fp16 query (GEMM A)
__device__ __half gAKh[MROWS * DM];   // fp16 key   (GEMM A)
__device__ __half gWh [3 * DM * DM];  // fp16 Wq,Wk,Wv (GEMM B)
__device__ float  gRes[MROWS * DM];
__device__ float  gPartS[64 * DM];
__device__ float  gPartQ[64 * DM];
__device__ float  gColA[DM];
__device__ float  gColB[DM];

// ---------------- helpers ----------------
static __device__ __forceinline__ uint32_t smem_u32(const void* p) {
    uint32_t r;
    asm("{ .reg .u64 t; cvta.to.shared.u64 t, %1; cvt.u32.u64 %0, t; }"
        : "=r"(r) : "l"(p));
    return r;
}
static __device__ __forceinline__ void mma_f16(float* d, const uint32_t* a,
                                               uint32_t b0, uint32_t b1)
{
    asm volatile(
        "mma.sync.aligned.m16n8k16.row.col.f32.f16.f16.f32 "
        "{%0,%1,%2,%3}, {%4,%5,%6,%7}, {%8,%9}, {%0,%1,%2,%3};"
        : "+f"(d[0]), "+f"(d[1]), "+f"(d[2]), "+f"(d[3])
        : "r"(a[0]), "r"(a[1]), "r"(a[2]), "r"(a[3]), "r"(b0), "r"(b1));
}
static __device__ __forceinline__ void ldsm_x4(uint32_t* r, uint32_t addr) {
    asm volatile("ldmatrix.sync.aligned.m8n8.x4.shared.b16 {%0,%1,%2,%3}, [%4];"
                 : "=r"(r[0]), "=r"(r[1]), "=r"(r[2]), "=r"(r[3]) : "r"(addr));
}
static __device__ __forceinline__ void ldsm_x2_t(uint32_t& r0, uint32_t& r1,
                                                 uint32_t addr)
{
    asm volatile("ldmatrix.sync.aligned.m8n8.x2.trans.shared.b16 {%0,%1}, [%2];"
                 : "=r"(r0), "=r"(r1) : "r"(addr));
}
static __device__ __forceinline__ float ex2f(float x) {
    float r;
    asm("ex2.approx.f32 %0, %1;" : "=f"(r) : "f"(x));
    return r;
}
// swizzled half-index within a tile of 64-half (128B) rows
#define SWH(r, hc) (((r) << 6) + (((hc) & 7) | ((((hc) >> 3) ^ ((r) & 7)) << 3)))

// ============================================================================
// fused f32 -> f16 conversion pre-pass (flat grid over 5 segments)
// ============================================================================
__global__ void __launch_bounds__(256) conv_all(const float* __restrict__ q,
                                                const float* __restrict__ k,
                                                const float* __restrict__ wq,
                                                const float* __restrict__ wk,
                                                const float* __restrict__ wv)
{
    const int b = blockIdx.x;
    const float* in;
    __half* out;
    int i;
    if (b < 8192)       { in = q;  out = gAQh;              i = b * 256; }
    else if (b < 16384) { in = k;  out = gAKh;              i = (b - 8192) * 256; }
    else if (b < 17408) { in = wq; out = gWh;               i = (b - 16384) * 256; }
    else if (b < 18432) { in = wk; out = gWh + DM * DM;     i = (b - 17408) * 256; }
    else                { in = wv; out = gWh + 2 * DM * DM; i = (b - 18432) * 256; }
    i += threadIdx.x;
    float4 v = ((const float4*)in)[i];
    __half2* o = (__half2*)out + 2 * (size_t)i;
    o[0] = __floats2half2_rn(v.x, v.y);
    o[1] = __floats2half2_rn(v.z, v.w);
}

// ============================================================================
// fp16 mma.sync GEMM NT: C[m][n] = f16( sum_k A[m][k] * W[n][k] )
// CTA 128x128, BK=64 halves, 256 threads (8 warps), warp tile 64x32,
// m16n8k16, cp.async double-buffered, XOR-swizzled smem, ldmatrix frags.
// ============================================================================
#define GSTG 8192   // halves per stage per matrix (128 rows x 64 halves)

__global__ void __launch_bounds__(256) gemm_mma()
{
    extern __shared__ __align__(16) __half smh[];
    const int tid  = threadIdx.x;
    const int lane = tid & 31;
    const int wid  = tid >> 5;
    const int g    = lane >> 2;
    const int tg   = lane & 3;
    const int wM   = wid >> 2;
    const int wN   = wid & 3;
    const int n0   = blockIdx.x * 128;
    const int m0   = blockIdx.y * 128;
    const int z    = blockIdx.z;

    const __half* __restrict__ A = (z == 0) ? gAQh : gAKh;
    const __half* __restrict__ W = gWh + (size_t)z * DM * DM;
    __half* __restrict__ C = (z == 0) ? gQh : ((z == 1) ? gKh : gVh);

    const uint32_t asA[2] = { smem_u32(smh),            smem_u32(smh + GSTG) };
    const uint32_t asB[2] = { smem_u32(smh + 2 * GSTG), smem_u32(smh + 3 * GSTG) };

    float acc[4][4][4] = {};

    const int lr  = tid >> 3;    // load row base 0..31
    const int lc8 = tid & 7;     // 16B chunk 0..7

    // ldmatrix lane-address components (fixed per thread)
    const int arow = lane & 15;              // A/P row within 16-row frag
    const int asel = lane >> 4;              // A chunk offset 0/1
    const int quad = lane >> 3;
    const int brow = ((quad >> 1) << 3) + (lane & 7);   // B row within 16
    const int bsel = quad & 1;               // B chunk offset 0/1

    {
        #pragma unroll
        for (int it = 0; it < 4; ++it) {
            int r = lr + it * 32;
            uint32_t off = (uint32_t)(r * 128 + ((lc8 ^ (r & 7)) << 4));
            const __half* sa = A + (size_t)(m0 + r) * DM + lc8 * 8;
            asm volatile("cp.async.cg.shared.global [%0], [%1], 16;"
                         :: "r"(asA[0] + off), "l"(sa));
            const __half* sb = W + (size_t)(n0 + r) * DM + lc8 * 8;
            asm volatile("cp.async.cg.shared.global [%0], [%1], 16;"
                         :: "r"(asB[0] + off), "l"(sb));
        }
        asm volatile("cp.async.commit_group;" ::: "memory");
    }

    const int NSTAGE = DM / 64;   // 16
    for (int s = 0; s < NSTAGE; ++s) {
        const int buf = s & 1;
        if (s + 1 < NSTAGE) {
            const int nb = buf ^ 1;
            const int k0 = (s + 1) * 64;
            #pragma unroll
            for (int it = 0; it < 4; ++it) {
                int r = lr + it * 32;
                uint32_t off = (uint32_t)(r * 128 + ((lc8 ^ (r & 7)) << 4));
                const __half* sa = A + (size_t)(m0 + r) * DM + k0 + lc8 * 8;
                asm volatile("cp.async.cg.shared.global [%0], [%1], 16;"
                             :: "r"(asA[nb] + off), "l"(sa));
                const __half* sb = W + (size_t)(n0 + r) * DM + k0 + lc8 * 8;
                asm volatile("cp.async.cg.shared.global [%0], [%1], 16;"
                             :: "r"(asB[nb] + off), "l"(sb));
            }
            asm volatile("cp.async.commit_group;" ::: "memory");
            asm volatile("cp.async.wait_group %0;" :: "n"(1) : "memory");
        } else {
            asm volatile("cp.async.wait_group %0;" :: "n"(0) : "memory");
        }
        __syncthreads();

        #pragma unroll
        for (int kk = 0; kk < 4; ++kk) {          // 4 x k16 = 64
            uint32_t af[4][4];
            const uint32_t ckA = (uint32_t)(2 * kk + asel);
            #pragma unroll
            for (int mt = 0; mt < 4; ++mt) {
                int row = wM * 64 + mt * 16 + arow;
                uint32_t addr = asA[buf] + (uint32_t)(row * 128)
                              + ((ckA ^ (uint32_t)(row & 7)) << 4);
                ldsm_x4(af[mt], addr);
            }
            uint32_t bf[4][2];
            const uint32_t ckB = (uint32_t)(2 * kk + bsel);
            #pragma unroll
            for (int np = 0; np < 2; ++np) {
                int row = wN * 32 + np * 16 + brow;
                uint32_t addr = asB[buf] + (uint32_t)(row * 128)
                              + ((ckB ^ (uint32_t)(row & 7)) << 4);
                uint32_t t[4];
                ldsm_x4(t, addr);
                bf[2 * np][0] = t[0]; bf[2 * np][1] = t[1];
                bf[2 * np + 1][0] = t[2]; bf[2 * np + 1][1] = t[3];
            }
            #pragma unroll
            for (int mt = 0; mt < 4; ++mt)
                #pragma unroll
                for (int nt = 0; nt < 4; ++nt)
                    mma_f16(acc[mt][nt], af[mt], bf[nt][0], bf[nt][1]);
        }
        __syncthreads();
    }

    // Epilogue: fp16 store
    #pragma unroll
    for (int mt = 0; mt < 4; ++mt) {
        int row = m0 + wM * 64 + mt * 16 + g;
        #pragma unroll
        for (int nt = 0; nt < 4; ++nt) {
            int col = n0 + wN * 32 + nt * 8 + tg * 2;
            *(__half2*)(C + (size_t)row * DM + col) =
                __floats2half2_rn(acc[mt][nt][0], acc[mt][nt][1]);
            *(__half2*)(C + (size_t)(row + 8) * DM + col) =
                __floats2half2_rn(acc[mt][nt][2], acc[mt][nt][3]);
        }
    }
}

// ============================================================================
// fp16 mma.sync causal flash attention.
// Q pre-scaled by (1/32)*log2(e) at staging -> softmax is pure ex2.approx.
// All fragment loads via ldmatrix. Smem 48KB.
// ============================================================================
__global__ void __launch_bounds__(128) attn_mma(const float* __restrict__ query)
{
    extern __shared__ __align__(16) __half ash[];
    __half* Kb[2] = { ash,         ash + 8192 };
    __half* Vb[2] = { ash + 4096,  ash + 12288 };
    __half* Ss    = ash + 16384;                 // 128 x 64 halves
    const uint32_t sK[2] = { smem_u32(Kb[0]), smem_u32(Kb[1]) };
    const uint32_t sV[2] = { smem_u32(Vb[0]), smem_u32(Vb[1]) };
    const uint32_t sS    = smem_u32(Ss);

    const int tid  = threadIdx.x;
    const int lane = tid & 31;
    const int wid  = tid >> 5;
    const int g    = lane >> 2;
    const int tg   = lane & 3;
    const int qt   = (int)(gridDim.x - 1) - (int)blockIdx.x;  // heavy-first
    const int h    = blockIdx.y;
    const int n    = blockIdx.z;

    const size_t nbase = (size_t)n * LQL * DM;
    const int hcol = h * PP;
    const int KT = 2 * qt + 2;

    // ldmatrix lane-address components
    const int arow = lane & 15;
    const int asel = lane >> 4;
    const int quad = lane >> 3;
    const int brow = ((quad >> 1) << 3) + (lane & 7);
    const int bsel = quad & 1;

    // ---- prefetch K/V tile 0 ----
    {
        const __half* Kg = gKh + nbase + hcol;
        const __half* Vg = gVh + nbase + hcol;
        #pragma unroll
        for (int i = 0; i < 4; ++i) {
            int idx = tid + i * 128;
            int r = idx >> 3, c8 = idx & 7;
            uint32_t off = (uint32_t)(r * 128 + ((c8 ^ (r & 7)) << 4));
            asm volatile("cp.async.cg.shared.global [%0], [%1], 16;"
                         :: "r"(sK[0] + off), "l"(Kg + (size_t)r * DM + c8 * 8));
            asm volatile("cp.async.cg.shared.global [%0], [%1], 16;"
                         :: "r"(sV[0] + off), "l"(Vg + (size_t)r * DM + c8 * 8));
        }
        asm volatile("cp.async.commit_group;" ::: "memory");
    }

    // ---- stage Q tile pre-scaled by (1/32)*log2e, then ldmatrix frags ----
    {
        const __half2 sc2 = __float2half2_rn(0.045084222f);  // 0.03125*log2(e)
        const __half* Qg = gQh + nbase + (size_t)qt * 128 * DM + hcol;
        #pragma unroll
        for (int i = 0; i < 8; ++i) {
            int idx = tid + i * 128;
            int r = idx >> 3, c8 = idx & 7;
            uint4 v = *(const uint4*)(Qg + (size_t)r * DM + c8 * 8);
            __half2* hv = (__half2*)&v;
            hv[0] = __hmul2(hv[0], sc2);
            hv[1] = __hmul2(hv[1], sc2);
            hv[2] = __hmul2(hv[2], sc2);
            hv[3] = __hmul2(hv[3], sc2);
            *(uint4*)(Ss + SWH(r, c8 * 8)) = v;
        }
    }
    __syncthreads();
    uint32_t qf[2][4][4];
    #pragma unroll
    for (int mb = 0; mb < 2; ++mb) {
        int row = wid * 32 + mb * 16 + arow;
        #pragma unroll
        for (int ks = 0; ks < 4; ++ks) {
            uint32_t ck = (uint32_t)(2 * ks + asel);
            uint32_t addr = sS + (uint32_t)(row * 128)
                          + ((ck ^ (uint32_t)(row & 7)) << 4);
            ldsm_x4(qf[mb][ks], addr);
        }
    }
    __syncthreads();

    float o[2][8][4] = {};
    float mrow[2][2], lrow[2][2];
    #pragma unroll
    for (int a = 0; a < 2; ++a)
        #pragma unroll
        for (int b = 0; b < 2; ++b) { mrow[a][b] = -INFINITY; lrow[a][b] = 0.f; }

    for (int kt = 0; kt < KT; ++kt) {
        const int buf = kt & 1;
        if (kt + 1 < KT) {
            const __half* Kg = gKh + nbase + (size_t)(kt + 1) * 64 * DM + hcol;
            const __half* Vg = gVh + nbase + (size_t)(kt + 1) * 64 * DM + hcol;
            #pragma unroll
            for (int i = 0; i < 4; ++i) {
                int idx = tid + i * 128;
                int r = idx >> 3, c8 = idx & 7;
                uint32_t off = (uint32_t)(r * 128 + ((c8 ^ (r & 7)) << 4));
                asm volatile("cp.async.cg.shared.global [%0], [%1], 16;"
                             :: "r"(sK[buf ^ 1] + off), "l"(Kg + (size_t)r * DM + c8 * 8));
                asm volatile("cp.async.cg.shared.global [%0], [%1], 16;"
                             :: "r"(sV[buf ^ 1] + off), "l"(Vg + (size_t)r * DM + c8 * 8));
            }
            asm volatile("cp.async.commit_group;" ::: "memory");
            asm volatile("cp.async.wait_group %0;" :: "n"(1) : "memory");
        } else {
            asm volatile("cp.async.wait_group %0;" :: "n"(0) : "memory");
        }
        __syncthreads();

        // ---- S = Q K^T (scores already in log2-units via prescaled Q) ----
        float s[2][8][4] = {};
        #pragma unroll
        for (int ks = 0; ks < 4; ++ks) {
            const uint32_t ck = (uint32_t)(2 * ks + bsel);
            #pragma unroll
            for (int nbp = 0; nbp < 4; ++nbp) {
                int row = nbp * 16 + brow;
                uint32_t addr = sK[buf] + (uint32_t)(row * 128)
                              + ((ck ^ (uint32_t)(row & 7)) << 4);
                uint32_t t[4];
                ldsm_x4(t, addr);
                mma_f16(s[0][2 * nbp],     qf[0][ks], t[0], t[1]);
                mma_f16(s[1][2 * nbp],     qf[1][ks], t[0], t[1]);
                mma_f16(s[0][2 * nbp + 1], qf[0][ks], t[2], t[3]);
                mma_f16(s[1][2 * nbp + 1], qf[1][ks], t[2], t[3]);
            }
        }

        // ---- mask + online softmax (pure ex2) ----
        const bool tail = (kt >= 2 * qt);
        #pragma unroll
        for (int mb = 0; mb < 2; ++mb) {
            #pragma unroll
            for (int rr = 0; rr < 2; ++rr) {
                const int grow = qt * 128 + wid * 32 + mb * 16 + rr * 8 + g;
                float tm = -INFINITY;
                #pragma unroll
                for (int nb = 0; nb < 8; ++nb) {
                    float v0 = s[mb][nb][rr * 2 + 0];
                    float v1 = s[mb][nb][rr * 2 + 1];
                    if (tail) {
                        int c0 = kt * 64 + nb * 8 + tg * 2;
                        if (c0     > grow) v0 = -1e30f;
                        if (c0 + 1 > grow) v1 = -1e30f;
                    }
                    s[mb][nb][rr * 2 + 0] = v0;
                    s[mb][nb][rr * 2 + 1] = v1;
                    tm = fmaxf(tm, fmaxf(v0, v1));
                }
                tm = fmaxf(tm, __shfl_xor_sync(0xffffffffu, tm, 1));
                tm = fmaxf(tm, __shfl_xor_sync(0xffffffffu, tm, 2));
                float nm   = fmaxf(mrow[mb][rr], tm);
                float corr = ex2f(mrow[mb][rr] - nm);
                mrow[mb][rr] = nm;
                float rs = 0.f;
                #pragma unroll
                for (int nb = 0; nb < 8; ++nb) {
                    float p0 = ex2f(s[mb][nb][rr * 2 + 0] - nm);
                    float p1 = ex2f(s[mb][nb][rr * 2 + 1] - nm);
                    s[mb][nb][rr * 2 + 0] = p0;
                    s[mb][nb][rr * 2 + 1] = p1;
                    rs += p0 + p1;
                }
                rs += __shfl_xor_sync(0xffffffffu, rs, 1);
                rs += __shfl_xor_sync(0xffffffffu, rs, 2);
                lrow[mb][rr] = lrow[mb][rr] * corr + rs;
                #pragma unroll
                for (int nb = 0; nb < 8; ++nb) {
                    o[mb][nb][rr * 2 + 0] *= corr;
                    o[mb][nb][rr * 2 + 1] *= corr;
                }
            }
        }

        // ---- store P (fp16) to Ss (warp-private rows) ----
        #pragma unroll
        for (int mb = 0; mb < 2; ++mb) {
            int r0 = wid * 32 + mb * 16 + g;
            #pragma unroll
            for (int nb = 0; nb < 8; ++nb) {
                *(__half2*)(Ss + SWH(r0,     nb * 8 + 2 * tg)) =
                    __floats2half2_rn(s[mb][nb][0], s[mb][nb][1]);
                *(__half2*)(Ss + SWH(r0 + 8, nb * 8 + 2 * tg)) =
                    __floats2half2_rn(s[mb][nb][2], s[mb][nb][3]);
            }
        }

        // ---- O += P V (P A-frags via ldmatrix, V via ldmatrix.trans) ----
        #pragma unroll
        for (int ks = 0; ks < 4; ++ks) {
            uint32_t af[2][4];
            const uint32_t ckP = (uint32_t)(2 * ks + asel);
            #pragma unroll
            for (int mb = 0; mb < 2; ++mb) {
                int row = wid * 32 + mb * 16 + arow;
                uint32_t addr = sS + (uint32_t)(row * 128)
                              + ((ckP ^ (uint32_t)(row & 7)) << 4);
                ldsm_x4(af[mb], addr);
            }
            const int vrow = ks * 16 + (lane & 15);
            const uint32_t rowbase = sV[buf] + (uint32_t)vrow * 128u;
            const uint32_t rx = (uint32_t)(vrow & 7) << 4;
            #pragma unroll
            for (int nb = 0; nb < 8; ++nb) {
                uint32_t addr = rowbase + (((uint32_t)nb << 4) ^ rx);
                uint32_t b0, b1;
                ldsm_x2_t(b0, b1, addr);
                mma_f16(o[0][nb], af[0], b0, b1);
                mma_f16(o[1][nb], af[1], b0, b1);
            }
        }
        __syncthreads();   // WAR before next prefetch overwrites buffers
    }

    // ---- epilogue: normalize, add residual (fp32), write gRes ----
    #pragma unroll
    for (int mb = 0; mb < 2; ++mb) {
        #pragma unroll
        for (int rr = 0; rr < 2; ++rr) {
            float inv = 1.0f / lrow[mb][rr];
            int grow = qt * 128 + wid * 32 + mb * 16 + rr * 8 + g;
            size_t rowoff = nbase + (size_t)grow * DM + hcol;
            #pragma unroll
            for (int nb = 0; nb < 8; ++nb) {
                int c = nb * 8 + tg * 2;
                float2 qv = *(const float2*)(query + rowoff + c);
                float2 w;
                w.x = o[mb][nb][rr * 2 + 0] * inv + qv.x;
                w.y = o[mb][nb][rr * 2 + 1] * inv + qv.y;
                *(float2*)(gRes + rowoff + c) = w;
            }
        }
    }
}

// ---------------------------------------------------------------------------
// BatchNorm: deterministic two-stage column stats + fused normalize
// ---------------------------------------------------------------------------
__global__ void __launch_bounds__(256) colstats_partial()
{
    const int col   = blockIdx.x * 256 + threadIdx.x;
    const int chunk = blockIdx.y;
    const float* base = gRes + (size_t)chunk * 128 * DM + col;
    float s = 0.f, q = 0.f;
    #pragma unroll 8
    for (int r = 0; r < 128; ++r) {
        float v = base[(size_t)r * DM];
        s += v;
        q += v * v;
    }
    gPartS[chunk * DM + col] = s;
    gPartQ[chunk * DM + col] = q;
}

__global__ void __launch_bounds__(256) colstats_final(const float* __restrict__ gamma,
                                                      const float* __restrict__ beta)
{
    const int cidx = threadIdx.x & 31;
    const int seg  = threadIdx.x >> 5;
    const int col  = blockIdx.x * 32 + cidx;
    float s = 0.f, q = 0.f;
    #pragma unroll
    for (int c = 0; c < 8; ++c) {
        int chunk = seg * 8 + c;
        s += gPartS[chunk * DM + col];
        q += gPartQ[chunk * DM + col];
    }
    __shared__ float shS[8][33], shQ[8][33];
    shS[seg][cidx] = s;
    shQ[seg][cidx] = q;
    __syncthreads();
    if (seg == 0) {
        float ts = 0.f, tq = 0.f;
        #pragma unroll
        for (int i = 0; i < 8; ++i) { ts += shS[i][cidx]; tq += shQ[i][cidx]; }
        const float invn = 1.0f / (float)MROWS;
        float mean = ts * invn;
        float var  = tq * invn - mean * mean;
        float inv  = rsqrtf(var + EPSBN);
        float a    = gamma[col] * inv;
        gColA[col] = a;
        gColB[col] = beta[col] - mean * a;
    }
}

__global__ void __launch_bounds__(256) normalize_kernel(float* __restrict__ out)
{
    const size_t idx = (size_t)blockIdx.x * 256 + threadIdx.x;
    float4 v = ((const float4*)gRes)[idx];
    int col = (int)((idx * 4) & (DM - 1));
    float4 r;
    r.x = v.x * gColA[col + 0] + gColB[col + 0];
    r.y = v.y * gColA[col + 1] + gColB[col + 1];
    r.z = v.z * gColA[col + 2] + gColB[col + 2];
    r.w = v.w * gColA[col + 3] + gColB[col + 3];
    ((float4*)out)[idx] = r;
}

// ---------------------------------------------------------------------------
extern "C" void kernel_launch(void* const* d_in, const int* in_sizes, int n_in,
                              void* d_out, int out_size)
{
    const float* query = (const float*)d_in[0];
    const float* key   = (const float*)d_in[1];
    const float* Wq    = (const float*)d_in[2];
    const float* Wk    = (const float*)d_in[3];
    const float* Wv    = (const float*)d_in[4];
    const float* gamma = (const float*)d_in[5];
    const float* beta  = (const float*)d_in[6];
    float* out = (float*)d_out;

    // fused fp16 conversion pre-pass: 2x8192 act blocks + 3x1024 weight blocks
    conv_all<<<19456, 256>>>(query, key, Wq, Wk, Wv);

    // fp16 projections
    const int gemm_smem = 4 * GSTG * 2;      // 65536 B
    cudaFuncSetAttribute(gemm_mma, cudaFuncAttributeMaxDynamicSharedMemorySize,
                         gemm_smem);
    dim3 gg(DM / 128, MROWS / 128, 3);
    gemm_mma<<<gg, 256, gemm_smem>>>();

    // fp16 flash attention
    const int attn_smem = 24576 * 2;         // 49152 B
    cudaFuncSetAttribute(attn_mma, cudaFuncAttributeMaxDynamicSharedMemorySize,
                         attn_smem);
    dim3 ga(LQL / 128, HH, NB);
    attn_mma<<<ga, 128, attn_smem>>>(query);

    colstats_partial<<<dim3(DM / 256, 64), 256>>>();
    colstats_final<<<DM / 32, 256>>>(gamma, beta);

    const int total_f4 = MROWS * DM / 4;
    normalize_kernel<<<total_f4 / 256, 256>>>(out);
}

// round 10
// speedup vs baseline: 2.0658x; 1.0198x over previous
#include <cuda_runtime.h>
#include <cuda_fp16.h>
#include <math.h>
#include <stdint.h>

// Problem constants (fixed shapes)
#define NB   4
#define LQL  2048
#define DM   1024
#define HH   16
#define PP   64
#define MROWS (NB*LQL)        // 8192
#define EPSBN 1e-5f

// ---------------- scratch (device globals: allocation-free) ----------------
__device__ __half gQh [MROWS * DM];
__device__ __half gKh [MROWS * DM];
__device__ __half gVh [MROWS * DM];
__device__ __half gAQh[MROWS * DM];
__device__ __half gAKh[MROWS * DM];
__device__ __half gWh [3 * DM * DM];
__device__ float  gRes[MROWS * DM];
__device__ float  gPartS[64 * DM];
__device__ float  gPartQ[64 * DM];
__device__ float  gColA[DM];
__device__ float  gColB[DM];

// ---------------- helpers ----------------
static __device__ __forceinline__ uint32_t smem_u32(const void* p) {
    uint32_t r;
    asm("{ .reg .u64 t; cvta.to.shared.u64 t, %1; cvt.u32.u64 %0, t; }"
        : "=r"(r) : "l"(p));
    return r;
}
static __device__ __forceinline__ void mma_f16(float* d, const uint32_t* a,
                                               uint32_t b0, uint32_t b1)
{
    asm volatile(
        "mma.sync.aligned.m16n8k16.row.col.f32.f16.f16.f32 "
        "{%0,%1,%2,%3}, {%4,%5,%6,%7}, {%8,%9}, {%0,%1,%2,%3};"
        : "+f"(d[0]), "+f"(d[1]), "+f"(d[2]), "+f"(d[3])
        : "r"(a[0]), "r"(a[1]), "r"(a[2]), "r"(a[3]), "r"(b0), "r"(b1));
}
static __device__ __forceinline__ void ldsm_x4(uint32_t* r, uint32_t addr) {
    asm volatile("ldmatrix.sync.aligned.m8n8.x4.shared.b16 {%0,%1,%2,%3}, [%4];"
                 : "=r"(r[0]), "=r"(r[1]), "=r"(r[2]), "=r"(r[3]) : "r"(addr));
}
static __device__ __forceinline__ void ldsm_x2_t(uint32_t& r0, uint32_t& r1,
                                                 uint32_t addr)
{
    asm volatile("ldmatrix.sync.aligned.m8n8.x2.trans.shared.b16 {%0,%1}, [%2];"
                 : "=r"(r0), "=r"(r1) : "r"(addr));
}
static __device__ __forceinline__ float ex2f(float x) {
    float r;
    asm("ex2.approx.f32 %0, %1;" : "=f"(r) : "f"(x));
    return r;
}
#define SWH(r, hc) (((r) << 6) + (((hc) & 7) | ((((hc) >> 3) ^ ((r) & 7)) << 3)))

// ============================================================================
// fused f32 -> f16 conversion pre-pass
// ============================================================================
__global__ void __launch_bounds__(256) conv_all(const float* __restrict__ q,
                                                const float* __restrict__ k,
                                                const float* __restrict__ wq,
                                                const float* __restrict__ wk,
                                                const float* __restrict__ wv)
{
    const int b = blockIdx.x;
    const float* in;
    __half* out;
    int i;
    if (b < 8192)       { in = q;  out = gAQh;              i = b * 256; }
    else if (b < 16384) { in = k;  out = gAKh;              i = (b - 8192) * 256; }
    else if (b < 17408) { in = wq; out = gWh;               i = (b - 16384) * 256; }
    else if (b < 18432) { in = wk; out = gWh + DM * DM;     i = (b - 17408) * 256; }
    else                { in = wv; out = gWh + 2 * DM * DM; i = (b - 18432) * 256; }
    i += threadIdx.x;
    float4 v = ((const float4*)in)[i];
    __half2* o = (__half2*)out + 2 * (size_t)i;
    o[0] = __floats2half2_rn(v.x, v.y);
    o[1] = __floats2half2_rn(v.z, v.w);
}

// ============================================================================
// fp16 mma.sync GEMM NT, 3-stage cp.async pipeline.
// CTA 128x128, BK=64, 256 threads, warp tile 64x32, ldmatrix fragments.
// ============================================================================
#define GSTG 8192   // halves per stage per matrix

__global__ void __launch_bounds__(256) gemm_mma()
{
    extern __shared__ __align__(16) __half smh[];
    const int tid  = threadIdx.x;
    const int lane = tid & 31;
    const int wid  = tid >> 5;
    const int g    = lane >> 2;
    const int tg   = lane & 3;
    const int wM   = wid >> 2;
    const int wN   = wid & 3;
    const int n0   = blockIdx.x * 128;
    const int m0   = blockIdx.y * 128;
    const int z    = blockIdx.z;

    const __half* __restrict__ A = (z == 0) ? gAQh : gAKh;
    const __half* __restrict__ W = gWh + (size_t)z * DM * DM;
    __half* __restrict__ C = (z == 0) ? gQh : ((z == 1) ? gKh : gVh);

    uint32_t asA[3], asB[3];
    #pragma unroll
    for (int i = 0; i < 3; ++i) {
        asA[i] = smem_u32(smh + i * GSTG);
        asB[i] = smem_u32(smh + (3 + i) * GSTG);
    }

    float acc[4][4][4] = {};

    const int lr  = tid >> 3;
    const int lc8 = tid & 7;
    const int arow = lane & 15;
    const int asel = lane >> 4;
    const int quad = lane >> 3;
    const int brow = ((quad >> 1) << 3) + (lane & 7);
    const int bsel = quad & 1;

    // prologue: stages 0 and 1
    #pragma unroll
    for (int ps = 0; ps < 2; ++ps) {
        const int k0 = ps * 64;
        #pragma unroll
        for (int it = 0; it < 4; ++it) {
            int r = lr + it * 32;
            uint32_t off = (uint32_t)(r * 128 + ((lc8 ^ (r & 7)) << 4));
            const __half* sa = A + (size_t)(m0 + r) * DM + k0 + lc8 * 8;
            asm volatile("cp.async.cg.shared.global [%0], [%1], 16;"
                         :: "r"(asA[ps] + off), "l"(sa));
            const __half* sb = W + (size_t)(n0 + r) * DM + k0 + lc8 * 8;
            asm volatile("cp.async.cg.shared.global [%0], [%1], 16;"
                         :: "r"(asB[ps] + off), "l"(sb));
        }
        asm volatile("cp.async.commit_group;" ::: "memory");
    }

    const int NSTAGE = DM / 64;   // 16
    int buf = 0, wbuf = 2;
    for (int s = 0; s < NSTAGE; ++s) {
        if (s + 2 < NSTAGE) {
            asm volatile("cp.async.wait_group %0;" :: "n"(1) : "memory");
        } else {
            asm volatile("cp.async.wait_group %0;" :: "n"(0) : "memory");
        }
        __syncthreads();

        if (s + 2 < NSTAGE) {
            const int k0 = (s + 2) * 64;
            #pragma unroll
            for (int it = 0; it < 4; ++it) {
                int r = lr + it * 32;
                uint32_t off = (uint32_t)(r * 128 + ((lc8 ^ (r & 7)) << 4));
                const __half* sa = A + (size_t)(m0 + r) * DM + k0 + lc8 * 8;
                asm volatile("cp.async.cg.shared.global [%0], [%1], 16;"
                             :: "r"(asA[wbuf] + off), "l"(sa));
                const __half* sb = W + (size_t)(n0 + r) * DM + k0 + lc8 * 8;
                asm volatile("cp.async.cg.shared.global [%0], [%1], 16;"
                             :: "r"(asB[wbuf] + off), "l"(sb));
            }
            asm volatile("cp.async.commit_group;" ::: "memory");
        }

        #pragma unroll
        for (int kk = 0; kk < 4; ++kk) {
            uint32_t af[4][4];
            const uint32_t ckA = (uint32_t)(2 * kk + asel);
            #pragma unroll
            for (int mt = 0; mt < 4; ++mt) {
                int row = wM * 64 + mt * 16 + arow;
                uint32_t addr = asA[buf] + (uint32_t)(row * 128)
                              + ((ckA ^ (uint32_t)(row & 7)) << 4);
                ldsm_x4(af[mt], addr);
            }
            uint32_t bf[4][2];
            const uint32_t ckB = (uint32_t)(2 * kk + bsel);
            #pragma unroll
            for (int np = 0; np < 2; ++np) {
                int row = wN * 32 + np * 16 + brow;
                uint32_t addr = asB[buf] + (uint32_t)(row * 128)
                              + ((ckB ^ (uint32_t)(row & 7)) << 4);
                uint32_t t[4];
                ldsm_x4(t, addr);
                bf[2 * np][0] = t[0]; bf[2 * np][1] = t[1];
                bf[2 * np + 1][0] = t[2]; bf[2 * np + 1][1] = t[3];
            }
            #pragma unroll
            for (int mt = 0; mt < 4; ++mt)
                #pragma unroll
                for (int nt = 0; nt < 4; ++nt)
                    mma_f16(acc[mt][nt], af[mt], bf[nt][0], bf[nt][1]);
        }
        buf = (buf + 1) % 3;
        wbuf = (wbuf + 1) % 3;
    }

    #pragma unroll
    for (int mt = 0; mt < 4; ++mt) {
        int row = m0 + wM * 64 + mt * 16 + g;
        #pragma unroll
        for (int nt = 0; nt < 4; ++nt) {
            int col = n0 + wN * 32 + nt * 8 + tg * 2;
            *(__half2*)(C + (size_t)row * DM + col) =
                __floats2half2_rn(acc[mt][nt][0], acc[mt][nt][1]);
            *(__half2*)(C + (size_t)(row + 8) * DM + col) =
                __floats2half2_rn(acc[mt][nt][2], acc[mt][nt][3]);
        }
    }
}

// ============================================================================
// fp16 mma.sync causal flash attention + FUSED BN column partial stats.
// Each CTA owns gRes rows [chunk*128, +128), cols [hcol, hcol+64):
// it writes gPartS/gPartQ[chunk*DM + hcol + c] directly (chunk = n*16+qt).
// ============================================================================
__global__ void __launch_bounds__(128) attn_mma(const float* __restrict__ query)
{
    extern __shared__ __align__(16) __half ash[];
    __half* Kb[2] = { ash,         ash + 8192 };
    __half* Vb[2] = { ash + 4096,  ash + 12288 };
    __half* Ss    = ash + 16384;
    const uint32_t sK[2] = { smem_u32(Kb[0]), smem_u32(Kb[1]) };
    const uint32_t sV[2] = { smem_u32(Vb[0]), smem_u32(Vb[1]) };
    const uint32_t sS    = smem_u32(Ss);

    const int tid  = threadIdx.x;
    const int lane = tid & 31;
    const int wid  = tid >> 5;
    const int g    = lane >> 2;
    const int tg   = lane & 3;
    const int qt   = (int)(gridDim.x - 1) - (int)blockIdx.x;  // heavy-first
    const int h    = blockIdx.y;
    const int n    = blockIdx.z;

    const size_t nbase = (size_t)n * LQL * DM;
    const int hcol = h * PP;
    const int KT = 2 * qt + 2;

    const int arow = lane & 15;
    const int asel = lane >> 4;
    const int quad = lane >> 3;
    const int brow = ((quad >> 1) << 3) + (lane & 7);
    const int bsel = quad & 1;

    {
        const __half* Kg = gKh + nbase + hcol;
        const __half* Vg = gVh + nbase + hcol;
        #pragma unroll
        for (int i = 0; i < 4; ++i) {
            int idx = tid + i * 128;
            int r = idx >> 3, c8 = idx & 7;
            uint32_t off = (uint32_t)(r * 128 + ((c8 ^ (r & 7)) << 4));
            asm volatile("cp.async.cg.shared.global [%0], [%1], 16;"
                         :: "r"(sK[0] + off), "l"(Kg + (size_t)r * DM + c8 * 8));
            asm volatile("cp.async.cg.shared.global [%0], [%1], 16;"
                         :: "r"(sV[0] + off), "l"(Vg + (size_t)r * DM + c8 * 8));
        }
        asm volatile("cp.async.commit_group;" ::: "memory");
    }

    {
        const __half2 sc2 = __float2half2_rn(0.045084222f);  // 0.03125*log2(e)
        const __half* Qg = gQh + nbase + (size_t)qt * 128 * DM + hcol;
        #pragma unroll
        for (int i = 0; i < 8; ++i) {
            int idx = tid + i * 128;
            int r = idx >> 3, c8 = idx & 7;
            uint4 v = *(const uint4*)(Qg + (size_t)r * DM + c8 * 8);
            __half2* hv = (__half2*)&v;
            hv[0] = __hmul2(hv[0], sc2);
            hv[1] = __hmul2(hv[1], sc2);
            hv[2] = __hmul2(hv[2], sc2);
            hv[3] = __hmul2(hv[3], sc2);
            *(uint4*)(Ss + SWH(r, c8 * 8)) = v;
        }
    }
    __syncthreads();
    uint32_t qf[2][4][4];
    #pragma unroll
    for (int mb = 0; mb < 2; ++mb) {
        int row = wid * 32 + mb * 16 + arow;
        #pragma unroll
        for (int ks = 0; ks < 4; ++ks) {
            uint32_t ck = (uint32_t)(2 * ks + asel);
            uint32_t addr = sS + (uint32_t)(row * 128)
                          + ((ck ^ (uint32_t)(row & 7)) << 4);
            ldsm_x4(qf[mb][ks], addr);
        }
    }
    __syncthreads();

    float o[2][8][4] = {};
    float mrow[2][2], lrow[2][2];
    #pragma unroll
    for (int a = 0; a < 2; ++a)
        #pragma unroll
        for (int b = 0; b < 2; ++b) { mrow[a][b] = -INFINITY; lrow[a][b] = 0.f; }

    for (int kt = 0; kt < KT; ++kt) {
        const int buf = kt & 1;
        if (kt + 1 < KT) {
            const __half* Kg = gKh + nbase + (size_t)(kt + 1) * 64 * DM + hcol;
            const __half* Vg = gVh + nbase + (size_t)(kt + 1) * 64 * DM + hcol;
            #pragma unroll
            for (int i = 0; i < 4; ++i) {
                int idx = tid + i * 128;
                int r = idx >> 3, c8 = idx & 7;
                uint32_t off = (uint32_t)(r * 128 + ((c8 ^ (r & 7)) << 4));
                asm volatile("cp.async.cg.shared.global [%0], [%1], 16;"
                             :: "r"(sK[buf ^ 1] + off), "l"(Kg + (size_t)r * DM + c8 * 8));
                asm volatile("cp.async.cg.shared.global [%0], [%1], 16;"
                             :: "r"(sV[buf ^ 1] + off), "l"(Vg + (size_t)r * DM + c8 * 8));
            }
            asm volatile("cp.async.commit_group;" ::: "memory");
            asm volatile("cp.async.wait_group %0;" :: "n"(1) : "memory");
        } else {
            asm volatile("cp.async.wait_group %0;" :: "n"(0) : "memory");
        }
        __syncthreads();

        float s[2][8][4] = {};
        #pragma unroll
        for (int ks = 0; ks < 4; ++ks) {
            const uint32_t ck = (uint32_t)(2 * ks + bsel);
            #pragma unroll
            for (int nbp = 0; nbp < 4; ++nbp) {
                int row = nbp * 16 + brow;
                uint32_t addr = sK[buf] + (uint32_t)(row * 128)
                              + ((ck ^ (uint32_t)(row & 7)) << 4);
                uint32_t t[4];
                ldsm_x4(t, addr);
                mma_f16(s[0][2 * nbp],     qf[0][ks], t[0], t[1]);
                mma_f16(s[1][2 * nbp],     qf[1][ks], t[0], t[1]);
                mma_f16(s[0][2 * nbp + 1], qf[0][ks], t[2], t[3]);
                mma_f16(s[1][2 * nbp + 1], qf[1][ks], t[2], t[3]);
            }
        }

        const bool tail = (kt >= 2 * qt);
        #pragma unroll
        for (int mb = 0; mb < 2; ++mb) {
            #pragma unroll
            for (int rr = 0; rr < 2; ++rr) {
                const int grow = qt * 128 + wid * 32 + mb * 16 + rr * 8 + g;
                float tm = -INFINITY;
                #pragma unroll
                for (int nb = 0; nb < 8; ++nb) {
                    float v0 = s[mb][nb][rr * 2 + 0];
                    float v1 = s[mb][nb][rr * 2 + 1];
                    if (tail) {
                        int c0 = kt * 64 + nb * 8 + tg * 2;
                        if (c0     > grow) v0 = -1e30f;
                        if (c0 + 1 > grow) v1 = -1e30f;
                    }
                    s[mb][nb][rr * 2 + 0] = v0;
                    s[mb][nb][rr * 2 + 1] = v1;
                    tm = fmaxf(tm, fmaxf(v0, v1));
                }
                tm = fmaxf(tm, __shfl_xor_sync(0xffffffffu, tm, 1));
                tm = fmaxf(tm, __shfl_xor_sync(0xffffffffu, tm, 2));
                float nm   = fmaxf(mrow[mb][rr], tm);
                float corr = ex2f(mrow[mb][rr] - nm);
                mrow[mb][rr] = nm;
                float rs = 0.f;
                #pragma unroll
                for (int nb = 0; nb < 8; ++nb) {
                    float p0 = ex2f(s[mb][nb][rr * 2 + 0] - nm);
                    float p1 = ex2f(s[mb][nb][rr * 2 + 1] - nm);
                    s[mb][nb][rr * 2 + 0] = p0;
                    s[mb][nb][rr * 2 + 1] = p1;
                    rs += p0 + p1;
                }
                rs += __shfl_xor_sync(0xffffffffu, rs, 1);
                rs += __shfl_xor_sync(0xffffffffu, rs, 2);
                lrow[mb][rr] = lrow[mb][rr] * corr + rs;
                #pragma unroll
                for (int nb = 0; nb < 8; ++nb) {
                    o[mb][nb][rr * 2 + 0] *= corr;
                    o[mb][nb][rr * 2 + 1] *= corr;
                }
            }
        }

        #pragma unroll
        for (int mb = 0; mb < 2; ++mb) {
            int r0 = wid * 32 + mb * 16 + g;
            #pragma unroll
            for (int nb = 0; nb < 8; ++nb) {
                *(__half2*)(Ss + SWH(r0,     nb * 8 + 2 * tg)) =
                    __floats2half2_rn(s[mb][nb][0], s[mb][nb][1]);
                *(__half2*)(Ss + SWH(r0 + 8, nb * 8 + 2 * tg)) =
                    __floats2half2_rn(s[mb][nb][2], s[mb][nb][3]);
            }
        }

        #pragma unroll
        for (int ks = 0; ks < 4; ++ks) {
            uint32_t af[2][4];
            const uint32_t ckP = (uint32_t)(2 * ks + asel);
            #pragma unroll
            for (int mb = 0; mb < 2; ++mb) {
                int row = wid * 32 + mb * 16 + arow;
                uint32_t addr = sS + (uint32_t)(row * 128)
                              + ((ckP ^ (uint32_t)(row & 7)) << 4);
                ldsm_x4(af[mb], addr);
            }
            const int vrow = ks * 16 + (lane & 15);
            const uint32_t rowbase = sV[buf] + (uint32_t)vrow * 128u;
            const uint32_t rx = (uint32_t)(vrow & 7) << 4;
            #pragma unroll
            for (int nb = 0; nb < 8; ++nb) {
                uint32_t addr = rowbase + (((uint32_t)nb << 4) ^ rx);
                uint32_t b0, b1;
                ldsm_x2_t(b0, b1, addr);
                mma_f16(o[0][nb], af[0], b0, b1);
                mma_f16(o[1][nb], af[1], b0, b1);
            }
        }
        __syncthreads();
    }

    // ---- epilogue: normalize, residual add, write gRes, fused col stats ----
    float colS[16], colQ[16];
    #pragma unroll
    for (int i = 0; i < 16; ++i) { colS[i] = 0.f; colQ[i] = 0.f; }

    #pragma unroll
    for (int mb = 0; mb < 2; ++mb) {
        #pragma unroll
        for (int rr = 0; rr < 2; ++rr) {
            float inv = 1.0f / lrow[mb][rr];
            int grow = qt * 128 + wid * 32 + mb * 16 + rr * 8 + g;
            size_t rowoff = nbase + (size_t)grow * DM + hcol;
            #pragma unroll
            for (int nb = 0; nb < 8; ++nb) {
                int c = nb * 8 + tg * 2;
                float2 qv = *(const float2*)(query + rowoff + c);
                float2 w;
                w.x = o[mb][nb][rr * 2 + 0] * inv + qv.x;
                w.y = o[mb][nb][rr * 2 + 1] * inv + qv.y;
                *(float2*)(gRes + rowoff + c) = w;
                colS[2 * nb]     += w.x;
                colQ[2 * nb]     += w.x * w.x;
                colS[2 * nb + 1] += w.y;
                colQ[2 * nb + 1] += w.y * w.y;
            }
        }
    }
    // reduce over g (lanes 4,8,16 apart) — deterministic fixed tree
    #pragma unroll
    for (int i = 0; i < 16; ++i) {
        #pragma unroll
        for (int off = 4; off < 32; off <<= 1) {
            colS[i] += __shfl_xor_sync(0xffffffffu, colS[i], off);
            colQ[i] += __shfl_xor_sync(0xffffffffu, colQ[i], off);
        }
    }
    // cross-warp reduce via smem (reuse ash; all smem reads done: loop ends with sync)
    float* redS = (float*)ash;          // [4][64]
    float* redQ = redS + 256;           // [4][64]
    if (g == 0) {
        #pragma unroll
        for (int i = 0; i < 16; ++i) {
            int c = (i >> 1) * 8 + tg * 2 + (i & 1);
            redS[wid * 64 + c] = colS[i];
            redQ[wid * 64 + c] = colQ[i];
        }
    }
    __syncthreads();
    if (tid < 64) {
        float s = redS[tid] + redS[64 + tid] + redS[128 + tid] + redS[192 + tid];
        float q = redQ[tid] + redQ[64 + tid] + redQ[128 + tid] + redQ[192 + tid];
        int chunk = n * 16 + qt;
        gPartS[chunk * DM + hcol + tid] = s;
        gPartQ[chunk * DM + hcol + tid] = q;
    }
}

// ---------------------------------------------------------------------------
// BatchNorm: final stats + fused normalize
// ---------------------------------------------------------------------------
__global__ void __launch_bounds__(256) colstats_final(const float* __restrict__ gamma,
                                                      const float* __restrict__ beta)
{
    const int cidx = threadIdx.x & 31;
    const int seg  = threadIdx.x >> 5;
    const int col  = blockIdx.x * 32 + cidx;
    float s = 0.f, q = 0.f;
    #pragma unroll
    for (int c = 0; c < 8; ++c) {
        int chunk = seg * 8 + c;
        s += gPartS[chunk * DM + col];
        q += gPartQ[chunk * DM + col];
    }
    __shared__ float shS[8][33], shQ[8][33];
    shS[seg][cidx] = s;
    shQ[seg][cidx] = q;
    __syncthreads();
    if (seg == 0) {
        float ts = 0.f, tq = 0.f;
        #pragma unroll
        for (int i = 0; i < 8; ++i) { ts += shS[i][cidx]; tq += shQ[i][cidx]; }
        const float invn = 1.0f / (float)MROWS;
        float mean = ts * invn;
        float var  = tq * invn - mean * mean;
        float inv  = rsqrtf(var + EPSBN);
        float a    = gamma[col] * inv;
        gColA[col] = a;
        gColB[col] = beta[col] - mean * a;
    }
}

__global__ void __launch_bounds__(256) normalize_kernel(float* __restrict__ out)
{
    const size_t idx = (size_t)blockIdx.x * 256 + threadIdx.x;
    float4 v = ((const float4*)gRes)[idx];
    int col = (int)((idx * 4) & (DM - 1));
    float4 r;
    r.x = v.x * gColA[col + 0] + gColB[col + 0];
    r.y = v.y * gColA[col + 1] + gColB[col + 1];
    r.z = v.z * gColA[col + 2] + gColB[col + 2];
    r.w = v.w * gColA[col + 3] + gColB[col + 3];
    ((float4*)out)[idx] = r;
}

// ---------------------------------------------------------------------------
extern "C" void kernel_launch(void* const* d_in, const int* in_sizes, int n_in,
                              void* d_out, int out_size)
{
    const float* query = (const float*)d_in[0];
    const float* key   = (const float*)d_in[1];
    const float* Wq    = (const float*)d_in[2];
    const float* Wk    = (const float*)d_in[3];
    const float* Wv    = (const float*)d_in[4];
    const float* gamma = (const float*)d_in[5];
    const float* beta  = (const float*)d_in[6];
    float* out = (float*)d_out;

    conv_all<<<19456, 256>>>(query, key, Wq, Wk, Wv);

    // fp16 projections, 3-stage pipeline
    const int gemm_smem = 6 * GSTG * 2;      // 98304 B
    cudaFuncSetAttribute(gemm_mma, cudaFuncAttributeMaxDynamicSharedMemorySize,
                         gemm_smem);
    dim3 gg(DM / 128, MROWS / 128, 3);
    gemm_mma<<<gg, 256, gemm_smem>>>();

    // fp16 flash attention + fused BN partial stats
    const int attn_smem = 24576 * 2;         // 49152 B
    cudaFuncSetAttribute(attn_mma, cudaFuncAttributeMaxDynamicSharedMemorySize,
                         attn_smem);
    dim3 ga(LQL / 128, HH, NB);
    attn_mma<<<ga, 128, attn_smem>>>(query);

    colstats_final<<<DM / 32, 256>>>(gamma, beta);

    const int total_f4 = MROWS * DM / 4;
    normalize_kernel<<<total_f4 / 256, 256>>>(out);
}

// round 11
// speedup vs baseline: 2.2611x; 1.0946x over previous
#include <cuda_runtime.h>
#include <cuda_fp16.h>
#include <math.h>
#include <stdint.h>

// Problem constants (fixed shapes)
#define NB   4
#define LQL  2048
#define DM   1024
#define HH   16
#define PP   64
#define MROWS (NB*LQL)        // 8192
#define EPSBN 1e-5f

// ---------------- scratch (device globals: allocation-free) ----------------
__device__ __half gQh [MROWS * DM];
__device__ __half gKh [MROWS * DM];
__device__ __half gVh [MROWS * DM];
__device__ __half gAQh[MROWS * DM];
__device__ __half gAKh[MROWS * DM];
__device__ __half gWh [3 * DM * DM];
__device__ float  gRes[MROWS * DM];
__device__ float  gPartS[64 * DM];
__device__ float  gPartQ[64 * DM];
__device__ float  gColA[DM];
__device__ float  gColB[DM];

// ---------------- helpers ----------------
static __device__ __forceinline__ uint32_t smem_u32(const void* p) {
    uint32_t r;
    asm("{ .reg .u64 t; cvta.to.shared.u64 t, %1; cvt.u32.u64 %0, t; }"
        : "=r"(r) : "l"(p));
    return r;
}
static __device__ __forceinline__ void mma_f16(float* d, const uint32_t* a,
                                               uint32_t b0, uint32_t b1)
{
    asm volatile(
        "mma.sync.aligned.m16n8k16.row.col.f32.f16.f16.f32 "
        "{%0,%1,%2,%3}, {%4,%5,%6,%7}, {%8,%9}, {%0,%1,%2,%3};"
        : "+f"(d[0]), "+f"(d[1]), "+f"(d[2]), "+f"(d[3])
        : "r"(a[0]), "r"(a[1]), "r"(a[2]), "r"(a[3]), "r"(b0), "r"(b1));
}
static __device__ __forceinline__ void ldsm_x4(uint32_t* r, uint32_t addr) {
    asm volatile("ldmatrix.sync.aligned.m8n8.x4.shared.b16 {%0,%1,%2,%3}, [%4];"
                 : "=r"(r[0]), "=r"(r[1]), "=r"(r[2]), "=r"(r[3]) : "r"(addr));
}
static __device__ __forceinline__ void ldsm_x2_t(uint32_t& r0, uint32_t& r1,
                                                 uint32_t addr)
{
    asm volatile("ldmatrix.sync.aligned.m8n8.x2.trans.shared.b16 {%0,%1}, [%2];"
                 : "=r"(r0), "=r"(r1) : "r"(addr));
}
static __device__ __forceinline__ float ex2f(float x) {
    float r;
    asm("ex2.approx.f32 %0, %1;" : "=f"(r) : "f"(x));
    return r;
}
static __device__ __forceinline__ uint32_t ex2h2(uint32_t x) {
    uint32_t r;
    asm("ex2.approx.f16x2 %0, %1;" : "=r"(r) : "r"(x));
    return r;
}
#define SWH(r, hc) (((r) << 6) + (((hc) & 7) | ((((hc) >> 3) ^ ((r) & 7)) << 3)))

// ============================================================================
// fused f32 -> f16 conversion pre-pass: 4 float4 per thread for BW
// ============================================================================
__global__ void __launch_bounds__(256) conv_all(const float* __restrict__ q,
                                                const float* __restrict__ k,
                                                const float* __restrict__ wq,
                                                const float* __restrict__ wk,
                                                const float* __restrict__ wv)
{
    const int b = blockIdx.x;
    const float* in;
    __half* out;
    int base;
    if (b < 2048)      { in = q;  out = gAQh;              base = b * 1024; }
    else if (b < 4096) { in = k;  out = gAKh;              base = (b - 2048) * 1024; }
    else if (b < 4352) { in = wq; out = gWh;               base = (b - 4096) * 1024; }
    else if (b < 4608) { in = wk; out = gWh + DM * DM;     base = (b - 4352) * 1024; }
    else               { in = wv; out = gWh + 2 * DM * DM; base = (b - 4608) * 1024; }
    #pragma unroll
    for (int j = 0; j < 4; ++j) {
        int i = base + j * 256 + threadIdx.x;
        float4 v = ((const float4*)in)[i];
        __half2* o = (__half2*)out + 2 * (size_t)i;
        o[0] = __floats2half2_rn(v.x, v.y);
        o[1] = __floats2half2_rn(v.z, v.w);
    }
}

// ============================================================================
// fp16 mma.sync GEMM NT, 3-stage cp.async pipeline.
// CTA 128x128, BK=64, 256 threads, warp tile 64x32, ldmatrix fragments.
// ============================================================================
#define GSTG 8192   // halves per stage per matrix

__global__ void __launch_bounds__(256) gemm_mma()
{
    extern __shared__ __align__(16) __half smh[];
    const int tid  = threadIdx.x;
    const int lane = tid & 31;
    const int wid  = tid >> 5;
    const int g    = lane >> 2;
    const int tg   = lane & 3;
    const int wM   = wid >> 2;
    const int wN   = wid & 3;
    const int n0   = blockIdx.x * 128;
    const int m0   = blockIdx.y * 128;
    const int z    = blockIdx.z;

    const __half* __restrict__ A = (z == 0) ? gAQh : gAKh;
    const __half* __restrict__ W = gWh + (size_t)z * DM * DM;
    __half* __restrict__ C = (z == 0) ? gQh : ((z == 1) ? gKh : gVh);

    uint32_t asA[3], asB[3];
    #pragma unroll
    for (int i = 0; i < 3; ++i) {
        asA[i] = smem_u32(smh + i * GSTG);
        asB[i] = smem_u32(smh + (3 + i) * GSTG);
    }

    float acc[4][4][4] = {};

    const int lr  = tid >> 3;
    const int lc8 = tid & 7;
    const int arow = lane & 15;
    const int asel = lane >> 4;
    const int quad = lane >> 3;
    const int brow = ((quad >> 1) << 3) + (lane & 7);
    const int bsel = quad & 1;

    #pragma unroll
    for (int ps = 0; ps < 2; ++ps) {
        const int k0 = ps * 64;
        #pragma unroll
        for (int it = 0; it < 4; ++it) {
            int r = lr + it * 32;
            uint32_t off = (uint32_t)(r * 128 + ((lc8 ^ (r & 7)) << 4));
            const __half* sa = A + (size_t)(m0 + r) * DM + k0 + lc8 * 8;
            asm volatile("cp.async.cg.shared.global [%0], [%1], 16;"
                         :: "r"(asA[ps] + off), "l"(sa));
            const __half* sb = W + (size_t)(n0 + r) * DM + k0 + lc8 * 8;
            asm volatile("cp.async.cg.shared.global [%0], [%1], 16;"
                         :: "r"(asB[ps] + off), "l"(sb));
        }
        asm volatile("cp.async.commit_group;" ::: "memory");
    }

    const int NSTAGE = DM / 64;   // 16
    int buf = 0, wbuf = 2;
    for (int s = 0; s < NSTAGE; ++s) {
        if (s + 2 < NSTAGE) {
            asm volatile("cp.async.wait_group %0;" :: "n"(1) : "memory");
        } else {
            asm volatile("cp.async.wait_group %0;" :: "n"(0) : "memory");
        }
        __syncthreads();

        if (s + 2 < NSTAGE) {
            const int k0 = (s + 2) * 64;
            #pragma unroll
            for (int it = 0; it < 4; ++it) {
                int r = lr + it * 32;
                uint32_t off = (uint32_t)(r * 128 + ((lc8 ^ (r & 7)) << 4));
                const __half* sa = A + (size_t)(m0 + r) * DM + k0 + lc8 * 8;
                asm volatile("cp.async.cg.shared.global [%0], [%1], 16;"
                             :: "r"(asA[wbuf] + off), "l"(sa));
                const __half* sb = W + (size_t)(n0 + r) * DM + k0 + lc8 * 8;
                asm volatile("cp.async.cg.shared.global [%0], [%1], 16;"
                             :: "r"(asB[wbuf] + off), "l"(sb));
            }
            asm volatile("cp.async.commit_group;" ::: "memory");
        }

        #pragma unroll
        for (int kk = 0; kk < 4; ++kk) {
            uint32_t af[4][4];
            const uint32_t ckA = (uint32_t)(2 * kk + asel);
            #pragma unroll
            for (int mt = 0; mt < 4; ++mt) {
                int row = wM * 64 + mt * 16 + arow;
                uint32_t addr = asA[buf] + (uint32_t)(row * 128)
                              + ((ckA ^ (uint32_t)(row & 7)) << 4);
                ldsm_x4(af[mt], addr);
            }
            uint32_t bf[4][2];
            const uint32_t ckB = (uint32_t)(2 * kk + bsel);
            #pragma unroll
            for (int np = 0; np < 2; ++np) {
                int row = wN * 32 + np * 16 + brow;
                uint32_t addr = asB[buf] + (uint32_t)(row * 128)
                              + ((ckB ^ (uint32_t)(row & 7)) << 4);
                uint32_t t[4];
                ldsm_x4(t, addr);
                bf[2 * np][0] = t[0]; bf[2 * np][1] = t[1];
                bf[2 * np + 1][0] = t[2]; bf[2 * np + 1][1] = t[3];
            }
            #pragma unroll
            for (int mt = 0; mt < 4; ++mt)
                #pragma unroll
                for (int nt = 0; nt < 4; ++nt)
                    mma_f16(acc[mt][nt], af[mt], bf[nt][0], bf[nt][1]);
        }
        buf = (buf + 1) % 3;
        wbuf = (wbuf + 1) % 3;
    }

    #pragma unroll
    for (int mt = 0; mt < 4; ++mt) {
        int row = m0 + wM * 64 + mt * 16 + g;
        #pragma unroll
        for (int nt = 0; nt < 4; ++nt) {
            int col = n0 + wN * 32 + nt * 8 + tg * 2;
            *(__half2*)(C + (size_t)row * DM + col) =
                __floats2half2_rn(acc[mt][nt][0], acc[mt][nt][1]);
            *(__half2*)(C + (size_t)(row + 8) * DM + col) =
                __floats2half2_rn(acc[mt][nt][2], acc[mt][nt][3]);
        }
    }
}

// ============================================================================
// fp16 mma.sync causal flash attention + fused BN partial stats.
// Softmax via ex2.approx.f16x2 (half the MUFU ops); P stored inline.
// ============================================================================
__global__ void __launch_bounds__(128) attn_mma(const float* __restrict__ query)
{
    extern __shared__ __align__(16) __half ash[];
    __half* Kb[2] = { ash,         ash + 8192 };
    __half* Vb[2] = { ash + 4096,  ash + 12288 };
    __half* Ss    = ash + 16384;
    const uint32_t sK[2] = { smem_u32(Kb[0]), smem_u32(Kb[1]) };
    const uint32_t sV[2] = { smem_u32(Vb[0]), smem_u32(Vb[1]) };
    const uint32_t sS    = smem_u32(Ss);

    const int tid  = threadIdx.x;
    const int lane = tid & 31;
    const int wid  = tid >> 5;
    const int g    = lane >> 2;
    const int tg   = lane & 3;
    const int qt   = (int)(gridDim.x - 1) - (int)blockIdx.x;  // heavy-first
    const int h    = blockIdx.y;
    const int n    = blockIdx.z;

    const size_t nbase = (size_t)n * LQL * DM;
    const int hcol = h * PP;
    const int KT = 2 * qt + 2;

    const int arow = lane & 15;
    const int asel = lane >> 4;
    const int quad = lane >> 3;
    const int brow = ((quad >> 1) << 3) + (lane & 7);
    const int bsel = quad & 1;

    {
        const __half* Kg = gKh + nbase + hcol;
        const __half* Vg = gVh + nbase + hcol;
        #pragma unroll
        for (int i = 0; i < 4; ++i) {
            int idx = tid + i * 128;
            int r = idx >> 3, c8 = idx & 7;
            uint32_t off = (uint32_t)(r * 128 + ((c8 ^ (r & 7)) << 4));
            asm volatile("cp.async.cg.shared.global [%0], [%1], 16;"
                         :: "r"(sK[0] + off), "l"(Kg + (size_t)r * DM + c8 * 8));
            asm volatile("cp.async.cg.shared.global [%0], [%1], 16;"
                         :: "r"(sV[0] + off), "l"(Vg + (size_t)r * DM + c8 * 8));
        }
        asm volatile("cp.async.commit_group;" ::: "memory");
    }

    {
        const __half2 sc2 = __float2half2_rn(0.045084222f);  // 0.03125*log2(e)
        const __half* Qg = gQh + nbase + (size_t)qt * 128 * DM + hcol;
        #pragma unroll
        for (int i = 0; i < 8; ++i) {
            int idx = tid + i * 128;
            int r = idx >> 3, c8 = idx & 7;
            uint4 v = *(const uint4*)(Qg + (size_t)r * DM + c8 * 8);
            __half2* hv = (__half2*)&v;
            hv[0] = __hmul2(hv[0], sc2);
            hv[1] = __hmul2(hv[1], sc2);
            hv[2] = __hmul2(hv[2], sc2);
            hv[3] = __hmul2(hv[3], sc2);
            *(uint4*)(Ss + SWH(r, c8 * 8)) = v;
        }
    }
    __syncthreads();
    uint32_t qf[2][4][4];
    #pragma unroll
    for (int mb = 0; mb < 2; ++mb) {
        int row = wid * 32 + mb * 16 + arow;
        #pragma unroll
        for (int ks = 0; ks < 4; ++ks) {
            uint32_t ck = (uint32_t)(2 * ks + asel);
            uint32_t addr = sS + (uint32_t)(row * 128)
                          + ((ck ^ (uint32_t)(row & 7)) << 4);
            ldsm_x4(qf[mb][ks], addr);
        }
    }
    __syncthreads();

    float o[2][8][4] = {};
    float mrow[2][2], lrow[2][2];
    #pragma unroll
    for (int a = 0; a < 2; ++a)
        #pragma unroll
        for (int b = 0; b < 2; ++b) { mrow[a][b] = -INFINITY; lrow[a][b] = 0.f; }

    for (int kt = 0; kt < KT; ++kt) {
        const int buf = kt & 1;
        if (kt + 1 < KT) {
            const __half* Kg = gKh + nbase + (size_t)(kt + 1) * 64 * DM + hcol;
            const __half* Vg = gVh + nbase + (size_t)(kt + 1) * 64 * DM + hcol;
            #pragma unroll
            for (int i = 0; i < 4; ++i) {
                int idx = tid + i * 128;
                int r = idx >> 3, c8 = idx & 7;
                uint32_t off = (uint32_t)(r * 128 + ((c8 ^ (r & 7)) << 4));
                asm volatile("cp.async.cg.shared.global [%0], [%1], 16;"
                             :: "r"(sK[buf ^ 1] + off), "l"(Kg + (size_t)r * DM + c8 * 8));
                asm volatile("cp.async.cg.shared.global [%0], [%1], 16;"
                             :: "r"(sV[buf ^ 1] + off), "l"(Vg + (size_t)r * DM + c8 * 8));
            }
            asm volatile("cp.async.commit_group;" ::: "memory");
            asm volatile("cp.async.wait_group %0;" :: "n"(1) : "memory");
        } else {
            asm volatile("cp.async.wait_group %0;" :: "n"(0) : "memory");
        }
        __syncthreads();

        float s[2][8][4] = {};
        #pragma unroll
        for (int ks = 0; ks < 4; ++ks) {
            const uint32_t ck = (uint32_t)(2 * ks + bsel);
            #pragma unroll
            for (int nbp = 0; nbp < 4; ++nbp) {
                int row = nbp * 16 + brow;
                uint32_t addr = sK[buf] + (uint32_t)(row * 128)
                              + ((ck ^ (uint32_t)(row & 7)) << 4);
                uint32_t t[4];
                ldsm_x4(t, addr);
                mma_f16(s[0][2 * nbp],     qf[0][ks], t[0], t[1]);
                mma_f16(s[1][2 * nbp],     qf[1][ks], t[0], t[1]);
                mma_f16(s[0][2 * nbp + 1], qf[0][ks], t[2], t[3]);
                mma_f16(s[1][2 * nbp + 1], qf[1][ks], t[2], t[3]);
            }
        }

        // ---- mask + online softmax (f16x2 ex2, P stored inline) ----
        const bool tail = (kt >= 2 * qt);
        #pragma unroll
        for (int mb = 0; mb < 2; ++mb) {
            #pragma unroll
            for (int rr = 0; rr < 2; ++rr) {
                const int rloc = wid * 32 + mb * 16 + rr * 8 + g;
                const int grow = qt * 128 + rloc;
                float tm = -INFINITY;
                #pragma unroll
                for (int nb = 0; nb < 8; ++nb) {
                    float v0 = s[mb][nb][rr * 2 + 0];
                    float v1 = s[mb][nb][rr * 2 + 1];
                    if (tail) {
                        int c0 = kt * 64 + nb * 8 + tg * 2;
                        if (c0     > grow) v0 = -1e30f;
                        if (c0 + 1 > grow) v1 = -1e30f;
                    }
                    s[mb][nb][rr * 2 + 0] = v0;
                    s[mb][nb][rr * 2 + 1] = v1;
                    tm = fmaxf(tm, fmaxf(v0, v1));
                }
                tm = fmaxf(tm, __shfl_xor_sync(0xffffffffu, tm, 1));
                tm = fmaxf(tm, __shfl_xor_sync(0xffffffffu, tm, 2));
                float nm   = fmaxf(mrow[mb][rr], tm);
                float corr = ex2f(mrow[mb][rr] - nm);
                mrow[mb][rr] = nm;
                float rs = 0.f;
                #pragma unroll
                for (int nb = 0; nb < 8; ++nb) {
                    __half2 a2 = __floats2half2_rn(s[mb][nb][rr * 2 + 0] - nm,
                                                   s[mb][nb][rr * 2 + 1] - nm);
                    uint32_t p2 = ex2h2(*(uint32_t*)&a2);
                    *(uint32_t*)(Ss + SWH(rloc, nb * 8 + 2 * tg)) = p2;
                    float2 pf = __half22float2(*(__half2*)&p2);
                    rs += pf.x + pf.y;
                }
                rs += __shfl_xor_sync(0xffffffffu, rs, 1);
                rs += __shfl_xor_sync(0xffffffffu, rs, 2);
                lrow[mb][rr] = lrow[mb][rr] * corr + rs;
                #pragma unroll
                for (int nb = 0; nb < 8; ++nb) {
                    o[mb][nb][rr * 2 + 0] *= corr;
                    o[mb][nb][rr * 2 + 1] *= corr;
                }
            }
        }

        // ---- O += P V (P A-frags via ldmatrix, V via ldmatrix.trans) ----
        #pragma unroll
        for (int ks = 0; ks < 4; ++ks) {
            uint32_t af[2][4];
            const uint32_t ckP = (uint32_t)(2 * ks + asel);
            #pragma unroll
            for (int mb = 0; mb < 2; ++mb) {
                int row = wid * 32 + mb * 16 + arow;
                uint32_t addr = sS + (uint32_t)(row * 128)
                              + ((ckP ^ (uint32_t)(row & 7)) << 4);
                ldsm_x4(af[mb], addr);
            }
            const int vrow = ks * 16 + (lane & 15);
            const uint32_t rowbase = sV[buf] + (uint32_t)vrow * 128u;
            const uint32_t rx = (uint32_t)(vrow & 7) << 4;
            #pragma unroll
            for (int nb = 0; nb < 8; ++nb) {
                uint32_t addr = rowbase + (((uint32_t)nb << 4) ^ rx);
                uint32_t b0, b1;
                ldsm_x2_t(b0, b1, addr);
                mma_f16(o[0][nb], af[0], b0, b1);
                mma_f16(o[1][nb], af[1], b0, b1);
            }
        }
        __syncthreads();
    }

    // ---- epilogue: normalize, residual add, write gRes, fused col stats ----
    float colS[16], colQ[16];
    #pragma unroll
    for (int i = 0; i < 16; ++i) { colS[i] = 0.f; colQ[i] = 0.f; }

    #pragma unroll
    for (int mb = 0; mb < 2; ++mb) {
        #pragma unroll
        for (int rr = 0; rr < 2; ++rr) {
            float inv = 1.0f / lrow[mb][rr];
            int grow = qt * 128 + wid * 32 + mb * 16 + rr * 8 + g;
            size_t rowoff = nbase + (size_t)grow * DM + hcol;
            #pragma unroll
            for (int nb = 0; nb < 8; ++nb) {
                int c = nb * 8 + tg * 2;
                float2 qv = *(const float2*)(query + rowoff + c);
                float2 w;
                w.x = o[mb][nb][rr * 2 + 0] * inv + qv.x;
                w.y = o[mb][nb][rr * 2 + 1] * inv + qv.y;
                *(float2*)(gRes + rowoff + c) = w;
                colS[2 * nb]     += w.x;
                colQ[2 * nb]     += w.x * w.x;
                colS[2 * nb + 1] += w.y;
                colQ[2 * nb + 1] += w.y * w.y;
            }
        }
    }
    #pragma unroll
    for (int i = 0; i < 16; ++i) {
        #pragma unroll
        for (int off = 4; off < 32; off <<= 1) {
            colS[i] += __shfl_xor_sync(0xffffffffu, colS[i], off);
            colQ[i] += __shfl_xor_sync(0xffffffffu, colQ[i], off);
        }
    }
    float* redS = (float*)ash;          // [4][64]
    float* redQ = redS + 256;           // [4][64]
    if (g == 0) {
        #pragma unroll
        for (int i = 0; i < 16; ++i) {
            int c = (i >> 1) * 8 + tg * 2 + (i & 1);
            redS[wid * 64 + c] = colS[i];
            redQ[wid * 64 + c] = colQ[i];
        }
    }
    __syncthreads();
    if (tid < 64) {
        float s = redS[tid] + redS[64 + tid] + redS[128 + tid] + redS[192 + tid];
        float q = redQ[tid] + redQ[64 + tid] + redQ[128 + tid] + redQ[192 + tid];
        int chunk = n * 16 + qt;
        gPartS[chunk * DM + hcol + tid] = s;
        gPartQ[chunk * DM + hcol + tid] = q;
    }
}

// ---------------------------------------------------------------------------
// BatchNorm: final stats + fused normalize
// ---------------------------------------------------------------------------
__global__ void __launch_bounds__(256) colstats_final(const float* __restrict__ gamma,
                                                      const float* __restrict__ beta)
{
    const int cidx = threadIdx.x & 31;
    const int seg  = threadIdx.x >> 5;
    const int col  = blockIdx.x * 32 + cidx;
    float s = 0.f, q = 0.f;
    #pragma unroll
    for (int c = 0; c < 8; ++c) {
        int chunk = seg * 8 + c;
        s += gPartS[chunk * DM + col];
        q += gPartQ[chunk * DM + col];
    }
    __shared__ float shS[8][33], shQ[8][33];
    shS[seg][cidx] = s;
    shQ[seg][cidx] = q;
    __syncthreads();
    if (seg == 0) {
        float ts = 0.f, tq = 0.f;
        #pragma unroll
        for (int i = 0; i < 8; ++i) { ts += shS[i][cidx]; tq += shQ[i][cidx]; }
        const float invn = 1.0f / (float)MROWS;
        float mean = ts * invn;
        float var  = tq * invn - mean * mean;
        float inv  = rsqrtf(var + EPSBN);
        float a    = gamma[col] * inv;
        gColA[col] = a;
        gColB[col] = beta[col] - mean * a;
    }
}

__global__ void __launch_bounds__(256) normalize_kernel(float* __restrict__ out)
{
    const size_t idx = (size_t)blockIdx.x * 256 + threadIdx.x;
    float4 v = ((const float4*)gRes)[idx];
    int col = (int)((idx * 4) & (DM - 1));
    float4 r;
    r.x = v.x * gColA[col + 0] + gColB[col + 0];
    r.y = v.y * gColA[col + 1] + gColB[col + 1];
    r.z = v.z * gColA[col + 2] + gColB[col + 2];
    r.w = v.w * gColA[col + 3] + gColB[col + 3];
    ((float4*)out)[idx] = r;
}

// ---------------------------------------------------------------------------
extern "C" void kernel_launch(void* const* d_in, const int* in_sizes, int n_in,
                              void* d_out, int out_size)
{
    const float* query = (const float*)d_in[0];
    const float* key   = (const float*)d_in[1];
    const float* Wq    = (const float*)d_in[2];
    const float* Wk    = (const float*)d_in[3];
    const float* Wv    = (const float*)d_in[4];
    const float* gamma = (const float*)d_in[5];
    const float* beta  = (const float*)d_in[6];
    float* out = (float*)d_out;

    conv_all<<<4864, 256>>>(query, key, Wq, Wk, Wv);

    const int gemm_smem = 6 * GSTG * 2;      // 98304 B
    cudaFuncSetAttribute(gemm_mma, cudaFuncAttributeMaxDynamicSharedMemorySize,
                         gemm_smem);
    dim3 gg(DM / 128, MROWS / 128, 3);
    gemm_mma<<<gg, 256, gemm_smem>>>();

    const int attn_smem = 24576 * 2;         // 49152 B
    cudaFuncSetAttribute(attn_mma, cudaFuncAttributeMaxDynamicSharedMemorySize,
                         attn_smem);
    dim3 ga(LQL / 128, HH, NB);
    attn_mma<<<ga, 128, attn_smem>>>(query);

    colstats_final<<<DM / 32, 256>>>(gamma, beta);

    const int total_f4 = MROWS * DM / 4;
    normalize_kernel<<<total_f4 / 256, 256>>>(out);
}